// round 5
// baseline (speedup 1.0000x reference)
#include <cuda_runtime.h>
#include <math.h>
#include <stdint.h>

#define Bb   8
#define Cch  128
#define Lsp  4096
#define CL   (Cch*Lsp)        // 524288
#define C4L  (4*CL)
#define BCL  (Bb*CL)

// ---------------- scratch (static device memory) ----------------------------
__device__ float g_y1[8*BCL];
__device__ float g_y2[8*BCL];
__device__ float g_q [BCL];
__device__ float g_KV[2*Bb*C4L];
__device__ float g_x [BCL];
__device__ float g_at[Bb*128*512];

__device__ __forceinline__ float gelu_exact(float x) {
    return 0.5f * x * (1.0f + erff(x * 0.70710678118654752f));
}

// ---- warp-level tf32 MMA: D(16x8) += A(16x8) * B(8x8) ----------------------
__device__ __forceinline__ void mma8(float* d,
    uint32_t a0, uint32_t a1, uint32_t a2, uint32_t a3,
    uint32_t b0, uint32_t b1)
{
    asm volatile(
        "mma.sync.aligned.m16n8k8.row.col.f32.tf32.tf32.f32 "
        "{%0,%1,%2,%3}, {%4,%5,%6,%7}, {%8,%9}, {%0,%1,%2,%3};"
        : "+f"(d[0]), "+f"(d[1]), "+f"(d[2]), "+f"(d[3])
        : "r"(a0), "r"(a1), "r"(a2), "r"(a3), "r"(b0), "r"(b1));
}

// 3xTF32 split: x ~= hi + lo, both tf32-representable
__device__ __forceinline__ uint32_t tf32r(float x) {
    uint32_t r; asm("cvt.rna.tf32.f32 %0, %1;" : "=r"(r) : "f"(x)); return r;
}
__device__ __forceinline__ void split32(float x, uint32_t& h, uint32_t& l) {
    h = tf32r(x);
    l = tf32r(x - __uint_as_float(h));
}

// acc += (Ah+Al)*(Bh+Bl) ~= Ah*Bl + Al*Bh + Ah*Bh
__device__ __forceinline__ void mma3(float* d,
    const uint32_t* ah, const uint32_t* al,
    uint32_t bh0, uint32_t bh1, uint32_t bl0, uint32_t bl1)
{
    mma8(d, ah[0], ah[1], ah[2], ah[3], bl0, bl1);
    mma8(d, al[0], al[1], al[2], al[3], bh0, bh1);
    mma8(d, ah[0], ah[1], ah[2], ah[3], bh0, bh1);
}

// ---------------------------------------------------------------------------
// Tensor-core fused pointwise block (3xTF32 mma.sync).
// A = tokens[128][128], B = W[128 out][128 in], C = [token][out].
// flags: bit0 in LN+GELU, bit1 out GELU, bit2 residual
// ---------------------------------------------------------------------------
#define PW_SMEM ((2*128*132 + 384) * 4)

__global__ __launch_bounds__(256) void pw_v5(
    const float* __restrict__ in0, const float* __restrict__ in1,
    const float* __restrict__ in2, const float* __restrict__ in3,
    int sel, long i2, long i1, long i0,
    const float* __restrict__ Wb, const float* __restrict__ biasb,
    const float* __restrict__ g1b, const float* __restrict__ b1b,
    const float* __restrict__ g2b, const float* __restrict__ b2b,
    int blk0,
    const float* __restrict__ res, long rbs,
    float* __restrict__ outb, long o2, long o1, long o0,
    int flags)
{
    extern __shared__ float sm[];
    float* As = sm;                  // [128][132]
    float* Ws = sm + 128 * 132;      // [128][132]
    float* ps = sm + 2 * 128 * 132;  // bias | go | bo

    const int tid = threadIdx.x;
    const int lane = tid & 31, wid = tid >> 5;
    const int gid = lane >> 2, tig = lane & 3;
    const int b = blockIdx.y, z = blockIdx.z;
    const int l0 = blockIdx.x * 128;
    const int blk = blk0 + z;
    const int zm = z & 3, zh = z >> 2;

    const float* inbase = sel ? (zm == 0 ? in0 : zm == 1 ? in1 : zm == 2 ? in2 : in3) : in0;
    const float* inp  = inbase + (long)zh * i2 + (long)zm * i1 + (long)b * i0 + l0;
    const float* W    = Wb + (long)blk * 128 * 128;
    const float* bias = biasb + blk * 128;
    const float* gi = g1b + blk * 128, *bi = b1b + blk * 128;
    const float* go = g2b + blk * 128, *bo = b2b + blk * 128;
    float* outp = outb + (long)zh * o2 + (long)zm * o1 + (long)b * o0 + l0;

    // ---- staging: warps 0-3 tokens (+optional LN+GELU), warps 4-7 weights --
    if (tid < 128) {
        const int t = tid;
        if (flags & 1) {
            float s = 0.f, q = 0.f;
#pragma unroll 4
            for (int c = 0; c < 128; c++) {
                float x = inp[(long)c * Lsp + t];
                As[t * 132 + c] = x; s += x; q += x * x;
            }
            float mean = s * (1.f / 128.f);
            float rstd = rsqrtf(q * (1.f / 128.f) - mean * mean + 1e-6f);
#pragma unroll 4
            for (int c4 = 0; c4 < 128; c4 += 4) {
                float4 v = *(float4*)&As[t * 132 + c4];
                v.x = gelu_exact((v.x - mean) * rstd * gi[c4 + 0] + bi[c4 + 0]);
                v.y = gelu_exact((v.y - mean) * rstd * gi[c4 + 1] + bi[c4 + 1]);
                v.z = gelu_exact((v.z - mean) * rstd * gi[c4 + 2] + bi[c4 + 2]);
                v.w = gelu_exact((v.w - mean) * rstd * gi[c4 + 3] + bi[c4 + 3]);
                *(float4*)&As[t * 132 + c4] = v;
            }
        } else {
#pragma unroll 4
            for (int c = 0; c < 128; c++)
                As[t * 132 + c] = inp[(long)c * Lsp + t];
        }
    } else {
        const int u = tid - 128;
#pragma unroll 4
        for (int i = 0; i < 32; i++) {
            int idx = u + i * 128;           // float4 index over 128x32
            int o = idx >> 5, c4 = idx & 31;
            float4 w = *(const float4*)&W[o * 128 + c4 * 4];
            *(float4*)&Ws[o * 132 + c4 * 4] = w;
        }
        ps[u] = bias[u]; ps[128 + u] = go[u]; ps[256 + u] = bo[u];
    }
    __syncthreads();

    // ---- MMA mainloop: warp (wm, wn) covers m=64, n=32 ----
    const int wm = wid >> 2, wn = wid & 3;
    const int m0b = wm * 64, n0b = wn * 32;
    float acc[16][4];
#pragma unroll
    for (int i = 0; i < 16; i++)
#pragma unroll
        for (int j = 0; j < 4; j++) acc[i][j] = 0.f;

    for (int k0 = 0; k0 < 128; k0 += 8) {
        uint32_t bh[4][2], bl[4][2];
#pragma unroll
        for (int nt = 0; nt < 4; nt++) {
            int n = n0b + nt * 8 + gid;
            split32(Ws[n * 132 + k0 + tig],     bh[nt][0], bl[nt][0]);
            split32(Ws[n * 132 + k0 + tig + 4], bh[nt][1], bl[nt][1]);
        }
#pragma unroll
        for (int mt = 0; mt < 4; mt++) {
            int m = m0b + mt * 16 + gid;
            uint32_t ah[4], al[4];
            split32(As[m * 132 + k0 + tig],           ah[0], al[0]);
            split32(As[(m + 8) * 132 + k0 + tig],     ah[1], al[1]);
            split32(As[m * 132 + k0 + tig + 4],       ah[2], al[2]);
            split32(As[(m + 8) * 132 + k0 + tig + 4], ah[3], al[3]);
#pragma unroll
            for (int nt = 0; nt < 4; nt++)
                mma3(acc[mt * 4 + nt], ah, al, bh[nt][0], bh[nt][1], bl[nt][0], bl[nt][1]);
        }
    }
    __syncthreads();

    // ---- C -> smem (reuse As) ----
#pragma unroll
    for (int mt = 0; mt < 4; mt++)
#pragma unroll
        for (int nt = 0; nt < 4; nt++) {
            int m = m0b + mt * 16 + gid;
            int n = n0b + nt * 8 + tig * 2;
            float* a = acc[mt * 4 + nt];
            *(float2*)&As[m * 132 + n] = make_float2(a[0], a[1]);
            *(float2*)&As[(m + 8) * 132 + n] = make_float2(a[2], a[3]);
        }
    __syncthreads();

    // ---- epilogue: thread t = token, +bias -> LN -> [GELU] -> [res] --------
    if (tid < 128) {
        const int t = tid;
        float s = 0.f, q = 0.f;
#pragma unroll 4
        for (int c = 0; c < 128; c++) {
            float v = As[t * 132 + c] + ps[c];
            s += v; q += v * v;
        }
        float mean = s * (1.f / 128.f);
        float rstd = rsqrtf(q * (1.f / 128.f) - mean * mean + 1e-6f);
        const float* resp = (flags & 4) ? (res + (long)b * rbs + l0) : nullptr;
#pragma unroll 4
        for (int c = 0; c < 128; c++) {
            float v = (As[t * 132 + c] + ps[c] - mean) * rstd * ps[128 + c] + ps[256 + c];
            if (flags & 2) v = gelu_exact(v);
            if (flags & 4) v += resp[(long)c * Lsp + t];
            outp[(long)c * Lsp + t] = v;
        }
    }
}

// ---------------------------------------------------------------------------
// qk: at[b][c][kt+n] = (1/64) sum_l q[b,c,l] K[b,kt+n,l]  (3xTF32)
// ---------------------------------------------------------------------------
#define QK_SMEM (2*128*132*4)
__global__ __launch_bounds__(256) void qk_mma(
    const float* __restrict__ q, const float* __restrict__ K,
    float* __restrict__ at)
{
    extern __shared__ float sm[];
    float* Qs = sm;
    float* Ks = sm + 128 * 132;
    const int tid = threadIdx.x;
    const int lane = tid & 31, wid = tid >> 5;
    const int gid = lane >> 2, tig = lane & 3;
    const int kt = blockIdx.x * 128;
    const int b = blockIdx.y;
    const float* qp = q + (long)b * CL;
    const float* Kp = K + (long)b * C4L + (long)kt * Lsp;

    const int wm = wid >> 2, wn = wid & 3;
    const int m0b = wm * 64, n0b = wn * 32;
    float acc[16][4];
#pragma unroll
    for (int i = 0; i < 16; i++)
#pragma unroll
        for (int j = 0; j < 4; j++) acc[i][j] = 0.f;

    for (int l0 = 0; l0 < Lsp; l0 += 128) {
        __syncthreads();
#pragma unroll 4
        for (int i = 0; i < 16; i++) {
            int idx = tid + i * 256;          // 4096 float4
            int r = idx >> 5, c4 = idx & 31;
            *(float4*)&Qs[r * 132 + c4 * 4] = *(const float4*)&qp[(long)r * Lsp + l0 + c4 * 4];
            *(float4*)&Ks[r * 132 + c4 * 4] = *(const float4*)&Kp[(long)r * Lsp + l0 + c4 * 4];
        }
        __syncthreads();
        for (int k0 = 0; k0 < 128; k0 += 8) {
            uint32_t bh[4][2], bl[4][2];
#pragma unroll
            for (int nt = 0; nt < 4; nt++) {
                int n = n0b + nt * 8 + gid;
                split32(Ks[n * 132 + k0 + tig],     bh[nt][0], bl[nt][0]);
                split32(Ks[n * 132 + k0 + tig + 4], bh[nt][1], bl[nt][1]);
            }
#pragma unroll
            for (int mt = 0; mt < 4; mt++) {
                int m = m0b + mt * 16 + gid;
                uint32_t ah[4], al[4];
                split32(Qs[m * 132 + k0 + tig],           ah[0], al[0]);
                split32(Qs[(m + 8) * 132 + k0 + tig],     ah[1], al[1]);
                split32(Qs[m * 132 + k0 + tig + 4],       ah[2], al[2]);
                split32(Qs[(m + 8) * 132 + k0 + tig + 4], ah[3], al[3]);
#pragma unroll
                for (int nt = 0; nt < 4; nt++)
                    mma3(acc[mt * 4 + nt], ah, al, bh[nt][0], bh[nt][1], bl[nt][0], bl[nt][1]);
            }
        }
    }
    float* ap = at + (long)b * 65536;
    const float sc = 0.015625f;
#pragma unroll
    for (int mt = 0; mt < 4; mt++)
#pragma unroll
        for (int nt = 0; nt < 4; nt++) {
            int m = m0b + mt * 16 + gid;
            int n = kt + n0b + nt * 8 + tig * 2;
            float* a = acc[mt * 4 + nt];
            *(float2*)&ap[(long)m * 512 + n] = make_float2(a[0] * sc, a[1] * sc);
            *(float2*)&ap[(long)(m + 8) * 512 + n] = make_float2(a[2] * sc, a[3] * sc);
        }
}

// ---------------------------------------------------------------------------
// masked softmax over 512 keys (input already scaled)
// ---------------------------------------------------------------------------
__global__ __launch_bounds__(128) void softmax_mask(
    float* __restrict__ at, const int* __restrict__ mask)
{
    __shared__ float sm[128];
    const int row = blockIdx.x;
    const int b = row >> 7;
    const int t = threadIdx.x;
    float* p0 = at + (long)row * 512;

    float v[4];
    float mx = -INFINITY;
#pragma unroll
    for (int j = 0; j < 4; j++) {
        bool on = mask[b * 4 + j] > 0;
        v[j] = on ? p0[j * 128 + t] : -INFINITY;
        mx = fmaxf(mx, v[j]);
    }
    sm[t] = mx; __syncthreads();
    for (int s = 64; s > 0; s >>= 1) {
        if (t < s) sm[t] = fmaxf(sm[t], sm[t + s]);
        __syncthreads();
    }
    mx = sm[0]; __syncthreads();

    float sum = 0.f;
#pragma unroll
    for (int j = 0; j < 4; j++) {
        v[j] = (v[j] == -INFINITY) ? 0.f : expf(v[j] - mx);
        sum += v[j];
    }
    sm[t] = sum; __syncthreads();
    for (int s = 64; s > 0; s >>= 1) {
        if (t < s) sm[t] += sm[t + s];
        __syncthreads();
    }
    float inv = 1.f / sm[0];
#pragma unroll
    for (int j = 0; j < 4; j++) p0[j * 128 + t] = v[j] * inv;
}

// ---------------------------------------------------------------------------
// av: x[b,c,lt+n] = sum_k attn[b,c,k] V[b,k,lt+n]  (3xTF32)
// ---------------------------------------------------------------------------
#define AV_SMEM ((128*68 + 64*136) * 4)
__global__ __launch_bounds__(256) void av_mma(
    const float* __restrict__ at, const float* __restrict__ V,
    float* __restrict__ xout)
{
    extern __shared__ float sm[];
    float* Aa = sm;                  // [128][68]
    float* Vs = sm + 128 * 68;       // [64][136]
    const int tid = threadIdx.x;
    const int lane = tid & 31, wid = tid >> 5;
    const int gid = lane >> 2, tig = lane & 3;
    const int lt = blockIdx.x * 128;
    const int b = blockIdx.y;
    const float* ap = at + (long)b * 65536;
    const float* Vp = V + (long)b * C4L;

    const int wm = wid >> 2, wn = wid & 3;
    const int m0b = wm * 64, n0b = wn * 32;
    float acc[16][4];
#pragma unroll
    for (int i = 0; i < 16; i++)
#pragma unroll
        for (int j = 0; j < 4; j++) acc[i][j] = 0.f;

    for (int kg = 0; kg < 512; kg += 64) {
        __syncthreads();
#pragma unroll 4
        for (int i = 0; i < 8; i++) {
            int idx = tid + i * 256;         // 2048 float4: attn 128x16
            int r = idx >> 4, c4 = idx & 15;
            *(float4*)&Aa[r * 68 + c4 * 4] = *(const float4*)&ap[(long)r * 512 + kg + c4 * 4];
        }
#pragma unroll 4
        for (int i = 0; i < 8; i++) {
            int idx = tid + i * 256;         // 2048 float4: V 64x32
            int r = idx >> 5, c4 = idx & 31;
            *(float4*)&Vs[r * 136 + c4 * 4] = *(const float4*)&Vp[(long)(kg + r) * Lsp + lt + c4 * 4];
        }
        __syncthreads();
        for (int k0 = 0; k0 < 64; k0 += 8) {
            uint32_t bh[4][2], bl[4][2];
#pragma unroll
            for (int nt = 0; nt < 4; nt++) {
                int n = n0b + nt * 8 + gid;
                split32(Vs[(k0 + tig) * 136 + n],     bh[nt][0], bl[nt][0]);
                split32(Vs[(k0 + tig + 4) * 136 + n], bh[nt][1], bl[nt][1]);
            }
#pragma unroll
            for (int mt = 0; mt < 4; mt++) {
                int m = m0b + mt * 16 + gid;
                uint32_t ah[4], al[4];
                split32(Aa[m * 68 + k0 + tig],           ah[0], al[0]);
                split32(Aa[(m + 8) * 68 + k0 + tig],     ah[1], al[1]);
                split32(Aa[m * 68 + k0 + tig + 4],       ah[2], al[2]);
                split32(Aa[(m + 8) * 68 + k0 + tig + 4], ah[3], al[3]);
#pragma unroll
                for (int nt = 0; nt < 4; nt++)
                    mma3(acc[mt * 4 + nt], ah, al, bh[nt][0], bh[nt][1], bl[nt][0], bl[nt][1]);
            }
        }
    }
    float* xp = xout + (long)b * CL + lt;
#pragma unroll
    for (int mt = 0; mt < 4; mt++)
#pragma unroll
        for (int nt = 0; nt < 4; nt++) {
            int m = m0b + mt * 16 + gid;
            int n = n0b + nt * 8 + tig * 2;
            float* a = acc[mt * 4 + nt];
            *(float2*)&xp[(long)m * Lsp + n] = make_float2(a[0], a[1]);
            *(float2*)&xp[(long)(m + 8) * Lsp + n] = make_float2(a[2], a[3]);
        }
}

// ---------------------------------------------------------------------------
// Depthwise 3x3x3 + bias (unchanged)
// ---------------------------------------------------------------------------
__global__ __launch_bounds__(256) void dw_v2(
    const float* __restrict__ inb, float* __restrict__ outb,
    long iz, long ib,
    const float* __restrict__ w27b, const float* __restrict__ biasb, int blk0)
{
    __shared__ float sp[16 * 324];
    const int tid = threadIdx.x;
    const int x = tid & 15, y = tid >> 4;
    const int c = blockIdx.x, b = blockIdx.y, z = blockIdx.z;
    const int blk = blk0 + z;

    const float* in = inb + (long)z * iz + (long)b * ib + (long)c * Lsp;
    float* out = outb + (long)z * iz + (long)b * ib + (long)c * Lsp;
    const float* wv = w27b + (long)blk * Cch * 27 + c * 27;
    const float bias = biasb[blk * Cch + c];

    for (int idx = tid; idx < 16 * 324; idx += 256) sp[idx] = 0.f;
    __syncthreads();
    for (int idx = tid; idx < 4096; idx += 256) {
        int zz = idx >> 8, rem = idx & 255;
        sp[zz * 324 + ((rem >> 4) + 1) * 18 + (rem & 15) + 1] = in[idx];
    }
    float w[27];
#pragma unroll
    for (int k = 0; k < 27; k++) w[k] = wv[k];
    __syncthreads();

    float p0[9], p1[9], p2[9];
#pragma unroll
    for (int k = 0; k < 9; k++) p0[k] = 0.f;
#pragma unroll
    for (int dy = 0; dy < 3; dy++)
#pragma unroll
        for (int dx = 0; dx < 3; dx++)
            p1[dy * 3 + dx] = sp[(y + dy) * 18 + (x + dx)];

#pragma unroll
    for (int zz = 0; zz < 16; zz++) {
        if (zz < 15) {
#pragma unroll
            for (int dy = 0; dy < 3; dy++)
#pragma unroll
                for (int dx = 0; dx < 3; dx++)
                    p2[dy * 3 + dx] = sp[(zz + 1) * 324 + (y + dy) * 18 + (x + dx)];
        } else {
#pragma unroll
            for (int k = 0; k < 9; k++) p2[k] = 0.f;
        }
        float a = bias;
#pragma unroll
        for (int k = 0; k < 9; k++) a += p0[k] * w[k];
#pragma unroll
        for (int k = 0; k < 9; k++) a += p1[k] * w[9 + k];
#pragma unroll
        for (int k = 0; k < 9; k++) a += p2[k] * w[18 + k];
        out[zz * 256 + tid] = a;
#pragma unroll
        for (int k = 0; k < 9; k++) { p0[k] = p1[k]; p1[k] = p2[k]; }
    }
}

// ---------------------------------------------------------------------------
extern "C" void kernel_launch(void* const* d_in, const int* in_sizes, int n_in,
                              void* d_out, int out_size)
{
    const float* query = (const float*)d_in[0];
    const float* m0 = (const float*)d_in[1];
    const float* m1 = (const float*)d_in[2];
    const float* m2 = (const float*)d_in[3];
    const float* m3 = (const float*)d_in[4];
    const int*   mask  = (const int*)d_in[5];
    const float* pw1_w = (const float*)d_in[6];
    const float* pw1_b = (const float*)d_in[7];
    const float* ln1_g = (const float*)d_in[8];
    const float* ln1_b = (const float*)d_in[9];
    const float* dw_w  = (const float*)d_in[10];
    const float* dw_b  = (const float*)d_in[11];
    const float* ln2_g = (const float*)d_in[12];
    const float* ln2_b = (const float*)d_in[13];
    const float* pw2_w = (const float*)d_in[14];
    const float* pw2_b = (const float*)d_in[15];
    const float* ln3_g = (const float*)d_in[16];
    const float* ln3_b = (const float*)d_in[17];
    float* out = (float*)d_out;

    float *y1, *y2, *qb, *kv, *xb, *at;
    cudaGetSymbolAddress((void**)&y1, g_y1);
    cudaGetSymbolAddress((void**)&y2, g_y2);
    cudaGetSymbolAddress((void**)&qb, g_q);
    cudaGetSymbolAddress((void**)&kv, g_KV);
    cudaGetSymbolAddress((void**)&xb, g_x);
    cudaGetSymbolAddress((void**)&at, g_at);
    float* Kb = kv;
    float* Vb = kv + (long)Bb * C4L;

    cudaFuncSetAttribute(pw_v5, cudaFuncAttributeMaxDynamicSharedMemorySize, PW_SMEM);
    cudaFuncSetAttribute(qk_mma, cudaFuncAttributeMaxDynamicSharedMemorySize, QK_SMEM);
    cudaFuncSetAttribute(av_mma, cudaFuncAttributeMaxDynamicSharedMemorySize, AV_SMEM);

    const long S2 = 4L * BCL, S1 = BCL, S0 = CL;
    const dim3 pw1_grid(32, Bb, 1);
    const dim3 pw8_grid(32, Bb, 8);

    // ---- query block (blk 0) ----
    pw_v5<<<pw1_grid, 256, PW_SMEM>>>(query, query, query, query, 0, 0, 0, CL,
        pw1_w, pw1_b, ln1_g, ln1_b, ln1_g, ln1_b, 0,
        nullptr, 0, y1, S2, S1, S0, 2);
    dw_v2<<<dim3(Cch, Bb, 1), 256>>>(y1, y2, BCL, CL, dw_w, dw_b, 0);
    pw_v5<<<pw1_grid, 256, PW_SMEM>>>(y2, y2, y2, y2, 0, S2, S1, S0,
        pw2_w, pw2_b, ln2_g, ln2_b, ln3_g, ln3_b, 0,
        nullptr, 0, qb, 0, 0, CL, 1);

    // ---- K/V blocks (blk 1..8), batched over grid.z ----
    pw_v5<<<pw8_grid, 256, PW_SMEM>>>(m0, m1, m2, m3, 1, 0, 0, CL,
        pw1_w, pw1_b, ln1_g, ln1_b, ln1_g, ln1_b, 1,
        nullptr, 0, y1, S2, S1, S0, 2);
    dw_v2<<<dim3(Cch, Bb, 8), 256>>>(y1, y2, BCL, CL, dw_w, dw_b, 1);
    pw_v5<<<pw8_grid, 256, PW_SMEM>>>(y2, y2, y2, y2, 0, S2, S1, S0,
        pw2_w, pw2_b, ln2_g, ln2_b, ln3_g, ln3_b, 1,
        nullptr, 0, kv, (long)Bb * C4L, CL, C4L, 1);

    // ---- attention ----
    qk_mma<<<dim3(4, Bb), 256, QK_SMEM>>>(qb, Kb, at);
    softmax_mask<<<Bb * 128, 128>>>(at, mask);
    av_mma<<<dim3(32, Bb), 256, AV_SMEM>>>(at, Vb, xb);

    // ---- out_project (blk 9) + residual ----
    pw_v5<<<pw1_grid, 256, PW_SMEM>>>(xb, xb, xb, xb, 0, 0, 0, CL,
        pw1_w, pw1_b, ln1_g, ln1_b, ln1_g, ln1_b, 9,
        nullptr, 0, y1, S2, S1, S0, 2);
    dw_v2<<<dim3(Cch, Bb, 1), 256>>>(y1, y2, BCL, CL, dw_w, dw_b, 9);
    pw_v5<<<pw1_grid, 256, PW_SMEM>>>(y2, y2, y2, y2, 0, S2, S1, S0,
        pw2_w, pw2_b, ln2_g, ln2_b, ln3_g, ln3_b, 9,
        query, CL, out, 0, 0, CL, 1 | 4);
}

// round 6
// speedup vs baseline: 2.3469x; 2.3469x over previous
#include <cuda_runtime.h>
#include <math.h>
#include <stdint.h>

#define Bb   8
#define Cch  128
#define Lsp  4096
#define CL   (Cch*Lsp)        // 524288
#define C4L  (4*CL)
#define BCL  (Bb*CL)

// ---------------- scratch (static device memory) ----------------------------
__device__ float g_y1[8*BCL];
__device__ float g_y2[8*BCL];
__device__ float g_q [BCL];
__device__ float g_KV[2*Bb*C4L];
__device__ float g_x [BCL];
__device__ float g_at [Bb*128*512];      // final softmax probs
__device__ float g_atp[4*Bb*128*512];    // qk partials (4 L-parts)

__device__ __forceinline__ float gelu_exact(float x) {
    return 0.5f * x * (1.0f + erff(x * 0.70710678118654752f));
}

// ======================= bf16 hi/lo packed ops ==============================
// pack: hi = bf16(x) in upper 16 bits, lo = bf16(x - hi) in lower 16 bits
__device__ __forceinline__ uint32_t packbf(float x) {
    uint16_t h, l;
    asm("cvt.rn.bf16.f32 %0, %1;" : "=h"(h) : "f"(x));
    float hf = __uint_as_float(((uint32_t)h) << 16);
    asm("cvt.rn.bf16.f32 %0, %1;" : "=h"(l) : "f"(x - hf));
    return ((uint32_t)h << 16) | (uint32_t)l;
}
// from two packed words (elem k, k+1): bf16x2 of hi parts / lo parts
__device__ __forceinline__ uint32_t hi2(uint2 P) { return __byte_perm(P.x, P.y, 0x7632); }
__device__ __forceinline__ uint32_t lo2(uint2 P) { return __byte_perm(P.x, P.y, 0x5410); }

// D(16x8) += A(16x16) * B(16x8), bf16 inputs, fp32 accum
__device__ __forceinline__ void mmabf(float* d,
    uint32_t a0, uint32_t a1, uint32_t a2, uint32_t a3, uint32_t b0, uint32_t b1)
{
    asm volatile(
        "mma.sync.aligned.m16n8k16.row.col.f32.bf16.bf16.f32 "
        "{%0,%1,%2,%3}, {%4,%5,%6,%7}, {%8,%9}, {%0,%1,%2,%3};"
        : "+f"(d[0]), "+f"(d[1]), "+f"(d[2]), "+f"(d[3])
        : "r"(a0), "r"(a1), "r"(a2), "r"(a3), "r"(b0), "r"(b1));
}
// acc += (Ah+Al)*(Bh+Bl) ~= Ah*Bl + Al*Bh + Ah*Bh
__device__ __forceinline__ void mma3bf(float* d,
    const uint32_t* ah, const uint32_t* al,
    uint32_t bh0, uint32_t bh1, uint32_t bl0, uint32_t bl1)
{
    mmabf(d, ah[0], ah[1], ah[2], ah[3], bl0, bl1);
    mmabf(d, al[0], al[1], al[2], al[3], bh0, bh1);
    mmabf(d, ah[0], ah[1], ah[2], ah[3], bh0, bh1);
}

// ---- tf32 helpers (kept for av kernel) -------------------------------------
__device__ __forceinline__ void mma8(float* d,
    uint32_t a0, uint32_t a1, uint32_t a2, uint32_t a3, uint32_t b0, uint32_t b1)
{
    asm volatile(
        "mma.sync.aligned.m16n8k8.row.col.f32.tf32.tf32.f32 "
        "{%0,%1,%2,%3}, {%4,%5,%6,%7}, {%8,%9}, {%0,%1,%2,%3};"
        : "+f"(d[0]), "+f"(d[1]), "+f"(d[2]), "+f"(d[3])
        : "r"(a0), "r"(a1), "r"(a2), "r"(a3), "r"(b0), "r"(b1));
}
__device__ __forceinline__ uint32_t tf32r(float x) {
    uint32_t r; asm("cvt.rna.tf32.f32 %0, %1;" : "=r"(r) : "f"(x)); return r;
}
__device__ __forceinline__ void split32(float x, uint32_t& h, uint32_t& l) {
    h = tf32r(x); l = tf32r(x - __uint_as_float(h));
}
__device__ __forceinline__ void mma3(float* d,
    const uint32_t* ah, const uint32_t* al,
    uint32_t bh0, uint32_t bh1, uint32_t bl0, uint32_t bl1)
{
    mma8(d, ah[0], ah[1], ah[2], ah[3], bl0, bl1);
    mma8(d, al[0], al[1], al[2], al[3], bh0, bh1);
    mma8(d, ah[0], ah[1], ah[2], ah[3], bh0, bh1);
}

// ---------------------------------------------------------------------------
// Fused pointwise block, packed-bf16 mma. 512 threads, 16 warps (m32 x n32).
// A = tokens[128][128], B = W[128 out][128 in], C = [token][out].
// flags: bit0 in LN+GELU, bit1 out GELU, bit2 residual
// ---------------------------------------------------------------------------
#define AS_STR 134
#define WS_STR 132
#define PW_SMEM ((128*AS_STR + 128*WS_STR + 1024 + 384) * 4)

__global__ __launch_bounds__(512) void pw_v6(
    const float* __restrict__ in0, const float* __restrict__ in1,
    const float* __restrict__ in2, const float* __restrict__ in3,
    int sel, long i2, long i1, long i0,
    const float* __restrict__ Wb, const float* __restrict__ biasb,
    const float* __restrict__ g1b, const float* __restrict__ b1b,
    const float* __restrict__ g2b, const float* __restrict__ b2b,
    int blk0,
    const float* __restrict__ res, long rbs,
    float* __restrict__ outb, long o2, long o1, long o0,
    int flags)
{
    extern __shared__ uint32_t smu[];
    uint32_t* As = smu;                       // [128][AS_STR] packed
    uint32_t* Ws = smu + 128 * AS_STR;        // [128][WS_STR] packed
    float* red = (float*)(smu + 128 * AS_STR + 128 * WS_STR);   // [2][4][128]
    float* ps  = red + 1024;                  // bias | go | bo
    float* Cs  = (float*)As;                  // epilogue alias

    const int tid = threadIdx.x;
    const int lane = tid & 31, wid = tid >> 5;
    const int gid = lane >> 2, tig = lane & 3;
    const int t = tid & 127, p = tid >> 7;
    const int cb = p * 32;
    const int b = blockIdx.y, z = blockIdx.z;
    const int l0 = blockIdx.x * 128;
    const int blk = blk0 + z;
    const int zm = z & 3, zh = z >> 2;

    const float* inbase = sel ? (zm == 0 ? in0 : zm == 1 ? in1 : zm == 2 ? in2 : in3) : in0;
    const float* inp  = inbase + (long)zh * i2 + (long)zm * i1 + (long)b * i0 + l0;
    const float* W    = Wb + (long)blk * 128 * 128;
    const float* bias = biasb + blk * 128;
    const float* gi = g1b + blk * 128, *bi = b1b + blk * 128;
    const float* go = g2b + blk * 128, *bo = b2b + blk * 128;
    float* outp = outb + (long)zh * o2 + (long)zm * o1 + (long)b * o0 + l0;

    // ---- A loads: 4 threads per token, 32 channels each (coalesced) ----
    float v[32];
    float s = 0.f, q = 0.f;
#pragma unroll
    for (int i = 0; i < 32; i++) {
        v[i] = inp[(long)(cb + i) * Lsp + t];
        s += v[i]; q += v[i] * v[i];
    }
    // ---- W staging: flat coalesced float4 -> packed uint4 ----
#pragma unroll
    for (int j = 0; j < 8; j++) {
        int idx = tid + j * 512;            // 4096 float4
        int o = idx >> 5, c4 = idx & 31;
        float4 w = *(const float4*)&W[o * 128 + c4 * 4];
        uint4 pw = make_uint4(packbf(w.x), packbf(w.y), packbf(w.z), packbf(w.w));
        *(uint4*)&Ws[o * WS_STR + c4 * 4] = pw;
    }
    if (tid < 128) { ps[tid] = bias[tid]; ps[128 + tid] = go[tid]; ps[256 + tid] = bo[tid]; }

    if (flags & 1) {
        red[p * 128 + t] = s; red[512 + p * 128 + t] = q;
        __syncthreads();
        float S = red[t] + red[128 + t] + red[256 + t] + red[384 + t];
        float Q = red[512 + t] + red[640 + t] + red[768 + t] + red[896 + t];
        float mean = S * (1.f / 128.f);
        float rstd = rsqrtf(Q * (1.f / 128.f) - mean * mean + 1e-6f);
#pragma unroll
        for (int i = 0; i < 32; i++) {
            float x = (v[i] - mean) * rstd * gi[cb + i] + bi[cb + i];
            As[t * AS_STR + cb + i] = packbf(gelu_exact(x));
        }
    } else {
#pragma unroll
        for (int i = 0; i < 32; i++)
            As[t * AS_STR + cb + i] = packbf(v[i]);
    }
    __syncthreads();

    // ---- mainloop: warp tile m32 x n32, k16 steps ----
    const int m0b = (wid >> 2) * 32, n0b = (wid & 3) * 32;
    float acc[8][4];
#pragma unroll
    for (int i = 0; i < 8; i++)
#pragma unroll
        for (int j = 0; j < 4; j++) acc[i][j] = 0.f;

#pragma unroll
    for (int k0 = 0; k0 < 128; k0 += 16) {
        const int ka = k0 + 2 * tig, kb = ka + 8;
        uint32_t bh[4][2], bl[4][2];
#pragma unroll
        for (int nt = 0; nt < 4; nt++) {
            int n = n0b + nt * 8 + gid;
            uint2 P0 = *(const uint2*)&Ws[n * WS_STR + ka];
            uint2 P1 = *(const uint2*)&Ws[n * WS_STR + kb];
            bh[nt][0] = hi2(P0); bl[nt][0] = lo2(P0);
            bh[nt][1] = hi2(P1); bl[nt][1] = lo2(P1);
        }
#pragma unroll
        for (int mt = 0; mt < 2; mt++) {
            int r0 = m0b + mt * 16 + gid, r1 = r0 + 8;
            uint2 Pa = *(const uint2*)&As[r0 * AS_STR + ka];
            uint2 Pb = *(const uint2*)&As[r1 * AS_STR + ka];
            uint2 Pc = *(const uint2*)&As[r0 * AS_STR + kb];
            uint2 Pd = *(const uint2*)&As[r1 * AS_STR + kb];
            uint32_t ah[4] = {hi2(Pa), hi2(Pb), hi2(Pc), hi2(Pd)};
            uint32_t al[4] = {lo2(Pa), lo2(Pb), lo2(Pc), lo2(Pd)};
#pragma unroll
            for (int nt = 0; nt < 4; nt++)
                mma3bf(acc[mt * 4 + nt], ah, al,
                       bh[nt][0], bh[nt][1], bl[nt][0], bl[nt][1]);
        }
    }
    __syncthreads();

    // ---- C -> smem (alias As) ----
#pragma unroll
    for (int mt = 0; mt < 2; mt++)
#pragma unroll
        for (int nt = 0; nt < 4; nt++) {
            int m = m0b + mt * 16 + gid, n = n0b + nt * 8 + tig * 2;
            float* a = acc[mt * 4 + nt];
            *(float2*)&Cs[m * AS_STR + n] = make_float2(a[0], a[1]);
            *(float2*)&Cs[(m + 8) * AS_STR + n] = make_float2(a[2], a[3]);
        }
    __syncthreads();

    // ---- epilogue: +bias -> LN -> [GELU] -> [res] ----
    float w2[32];
    float s2 = 0.f, q2 = 0.f;
#pragma unroll
    for (int i = 0; i < 32; i++) {
        w2[i] = Cs[t * AS_STR + cb + i] + ps[cb + i];
        s2 += w2[i]; q2 += w2[i] * w2[i];
    }
    red[p * 128 + t] = s2; red[512 + p * 128 + t] = q2;
    __syncthreads();
    float S2 = red[t] + red[128 + t] + red[256 + t] + red[384 + t];
    float Q2 = red[512 + t] + red[640 + t] + red[768 + t] + red[896 + t];
    float mean2 = S2 * (1.f / 128.f);
    float rstd2 = rsqrtf(Q2 * (1.f / 128.f) - mean2 * mean2 + 1e-6f);
    const float* resp = (flags & 4) ? (res + (long)b * rbs + l0) : nullptr;
#pragma unroll
    for (int i = 0; i < 32; i++) {
        int c = cb + i;
        float val = (w2[i] - mean2) * rstd2 * ps[128 + c] + ps[256 + c];
        if (flags & 2) val = gelu_exact(val);
        if (flags & 4) val += resp[(long)c * Lsp + t];
        outp[(long)c * Lsp + t] = val;
    }
}

// ---------------------------------------------------------------------------
// qk partial: atp[lp][b][c][kt+n] = sum over L-part of q[c,l]*K[k,l]
// packed-bf16 mma, 512 threads, tile 128c x 128k, grid (4 kt, 4 lp, 8 b)
// ---------------------------------------------------------------------------
#define QK_SMEM (2*128*WS_STR*4)
__global__ __launch_bounds__(512) void qk_v6(
    const float* __restrict__ q, const float* __restrict__ K,
    float* __restrict__ atp)
{
    extern __shared__ uint32_t smu[];
    uint32_t* Qs = smu;
    uint32_t* Ks = smu + 128 * WS_STR;
    const int tid = threadIdx.x;
    const int lane = tid & 31, wid = tid >> 5;
    const int gid = lane >> 2, tig = lane & 3;
    const int kt = blockIdx.x * 128, lp = blockIdx.y, b = blockIdx.z;
    const float* qp = q + (long)b * CL;
    const float* Kp = K + (long)b * C4L + (long)kt * Lsp;
    const int lbase = lp * 1024;

    const int m0b = (wid >> 2) * 32, n0b = (wid & 3) * 32;
    float acc[8][4];
#pragma unroll
    for (int i = 0; i < 8; i++)
#pragma unroll
        for (int j = 0; j < 4; j++) acc[i][j] = 0.f;

    for (int lc = 0; lc < 1024; lc += 128) {
        const int l0 = lbase + lc;
        __syncthreads();
#pragma unroll
        for (int j = 0; j < 8; j++) {
            int idx = tid + j * 512;
            int r = idx >> 5, c4 = idx & 31;
            float4 a = *(const float4*)&qp[(long)r * Lsp + l0 + c4 * 4];
            *(uint4*)&Qs[r * WS_STR + c4 * 4] =
                make_uint4(packbf(a.x), packbf(a.y), packbf(a.z), packbf(a.w));
            float4 kk = *(const float4*)&Kp[(long)r * Lsp + l0 + c4 * 4];
            *(uint4*)&Ks[r * WS_STR + c4 * 4] =
                make_uint4(packbf(kk.x), packbf(kk.y), packbf(kk.z), packbf(kk.w));
        }
        __syncthreads();
#pragma unroll
        for (int k0 = 0; k0 < 128; k0 += 16) {
            const int ka = k0 + 2 * tig, kb = ka + 8;
            uint32_t bh[4][2], bl[4][2];
#pragma unroll
            for (int nt = 0; nt < 4; nt++) {
                int n = n0b + nt * 8 + gid;
                uint2 P0 = *(const uint2*)&Ks[n * WS_STR + ka];
                uint2 P1 = *(const uint2*)&Ks[n * WS_STR + kb];
                bh[nt][0] = hi2(P0); bl[nt][0] = lo2(P0);
                bh[nt][1] = hi2(P1); bl[nt][1] = lo2(P1);
            }
#pragma unroll
            for (int mt = 0; mt < 2; mt++) {
                int r0 = m0b + mt * 16 + gid, r1 = r0 + 8;
                uint2 Pa = *(const uint2*)&Qs[r0 * WS_STR + ka];
                uint2 Pb = *(const uint2*)&Qs[r1 * WS_STR + ka];
                uint2 Pc = *(const uint2*)&Qs[r0 * WS_STR + kb];
                uint2 Pd = *(const uint2*)&Qs[r1 * WS_STR + kb];
                uint32_t ah[4] = {hi2(Pa), hi2(Pb), hi2(Pc), hi2(Pd)};
                uint32_t al[4] = {lo2(Pa), lo2(Pb), lo2(Pc), lo2(Pd)};
#pragma unroll
                for (int nt = 0; nt < 4; nt++)
                    mma3bf(acc[mt * 4 + nt], ah, al,
                           bh[nt][0], bh[nt][1], bl[nt][0], bl[nt][1]);
            }
        }
    }
    float* ap = atp + (long)lp * (Bb * 65536) + (long)b * 65536;
#pragma unroll
    for (int mt = 0; mt < 2; mt++)
#pragma unroll
        for (int nt = 0; nt < 4; nt++) {
            int m = m0b + mt * 16 + gid;
            int n = kt + n0b + nt * 8 + tig * 2;
            float* a = acc[mt * 4 + nt];
            *(float2*)&ap[(long)m * 512 + n] = make_float2(a[0], a[1]);
            *(float2*)&ap[(long)(m + 8) * 512 + n] = make_float2(a[2], a[3]);
        }
}

// ---------------------------------------------------------------------------
// masked softmax: sums 4 qk partials, scales by 1/64, writes probs to at
// ---------------------------------------------------------------------------
__global__ __launch_bounds__(128) void softmax_v6(
    const float* __restrict__ atp, float* __restrict__ at,
    const int* __restrict__ mask)
{
    __shared__ float sm[128];
    const int row = blockIdx.x;          // b*128 + c
    const int b = row >> 7;
    const int t = threadIdx.x;
    const float sc = 0.015625f;
    const long roff = (long)row * 512;
    const long pstr = (long)Bb * 65536;

    float v[4];
    float mx = -INFINITY;
#pragma unroll
    for (int j = 0; j < 4; j++) {
        bool on = mask[b * 4 + j] > 0;
        float sum = atp[roff + j * 128 + t] + atp[pstr + roff + j * 128 + t]
                  + atp[2 * pstr + roff + j * 128 + t] + atp[3 * pstr + roff + j * 128 + t];
        v[j] = on ? sum * sc : -INFINITY;
        mx = fmaxf(mx, v[j]);
    }
    sm[t] = mx; __syncthreads();
    for (int s = 64; s > 0; s >>= 1) {
        if (t < s) sm[t] = fmaxf(sm[t], sm[t + s]);
        __syncthreads();
    }
    mx = sm[0]; __syncthreads();

    float sum = 0.f;
#pragma unroll
    for (int j = 0; j < 4; j++) {
        v[j] = (v[j] == -INFINITY) ? 0.f : expf(v[j] - mx);
        sum += v[j];
    }
    sm[t] = sum; __syncthreads();
    for (int s = 64; s > 0; s >>= 1) {
        if (t < s) sm[t] += sm[t + s];
        __syncthreads();
    }
    float inv = 1.f / sm[0];
#pragma unroll
    for (int j = 0; j < 4; j++) at[roff + j * 128 + t] = v[j] * inv;
}

// ---------------------------------------------------------------------------
// av: x[b,c,lt+n] = sum_k attn[b,c,k] V[b,k,lt+n]  (3xTF32, unchanged)
// ---------------------------------------------------------------------------
#define AV_SMEM ((128*68 + 64*136) * 4)
__global__ __launch_bounds__(256) void av_mma(
    const float* __restrict__ at, const float* __restrict__ V,
    float* __restrict__ xout)
{
    extern __shared__ float sm[];
    float* Aa = sm;                  // [128][68]
    float* Vs = sm + 128 * 68;       // [64][136]
    const int tid = threadIdx.x;
    const int lane = tid & 31, wid = tid >> 5;
    const int gid = lane >> 2, tig = lane & 3;
    const int lt = blockIdx.x * 128;
    const int b = blockIdx.y;
    const float* ap = at + (long)b * 65536;
    const float* Vp = V + (long)b * C4L;

    const int wm = wid >> 2, wn = wid & 3;
    const int m0b = wm * 64, n0b = wn * 32;
    float acc[16][4];
#pragma unroll
    for (int i = 0; i < 16; i++)
#pragma unroll
        for (int j = 0; j < 4; j++) acc[i][j] = 0.f;

    for (int kg = 0; kg < 512; kg += 64) {
        __syncthreads();
#pragma unroll 4
        for (int i = 0; i < 8; i++) {
            int idx = tid + i * 256;
            int r = idx >> 4, c4 = idx & 15;
            *(float4*)&Aa[r * 68 + c4 * 4] = *(const float4*)&ap[(long)r * 512 + kg + c4 * 4];
        }
#pragma unroll 4
        for (int i = 0; i < 8; i++) {
            int idx = tid + i * 256;
            int r = idx >> 5, c4 = idx & 31;
            *(float4*)&Vs[r * 136 + c4 * 4] =
                *(const float4*)&Vp[(long)(kg + r) * Lsp + lt + c4 * 4];
        }
        __syncthreads();
        for (int k0 = 0; k0 < 64; k0 += 8) {
            uint32_t bh[4][2], bl[4][2];
#pragma unroll
            for (int nt = 0; nt < 4; nt++) {
                int n = n0b + nt * 8 + gid;
                split32(Vs[(k0 + tig) * 136 + n],     bh[nt][0], bl[nt][0]);
                split32(Vs[(k0 + tig + 4) * 136 + n], bh[nt][1], bl[nt][1]);
            }
#pragma unroll
            for (int mt = 0; mt < 4; mt++) {
                int m = m0b + mt * 16 + gid;
                uint32_t ah[4], al[4];
                split32(Aa[m * 68 + k0 + tig],           ah[0], al[0]);
                split32(Aa[(m + 8) * 68 + k0 + tig],     ah[1], al[1]);
                split32(Aa[m * 68 + k0 + tig + 4],       ah[2], al[2]);
                split32(Aa[(m + 8) * 68 + k0 + tig + 4], ah[3], al[3]);
#pragma unroll
                for (int nt = 0; nt < 4; nt++)
                    mma3(acc[mt * 4 + nt], ah, al,
                         bh[nt][0], bh[nt][1], bl[nt][0], bl[nt][1]);
            }
        }
    }
    float* xp = xout + (long)b * CL + lt;
#pragma unroll
    for (int mt = 0; mt < 4; mt++)
#pragma unroll
        for (int nt = 0; nt < 4; nt++) {
            int m = m0b + mt * 16 + gid;
            int n = n0b + nt * 8 + tig * 2;
            float* a = acc[mt * 4 + nt];
            *(float2*)&xp[(long)m * Lsp + n] = make_float2(a[0], a[1]);
            *(float2*)&xp[(long)(m + 8) * Lsp + n] = make_float2(a[2], a[3]);
        }
}

// ---------------------------------------------------------------------------
// Depthwise 3x3x3 + bias (unchanged)
// ---------------------------------------------------------------------------
__global__ __launch_bounds__(256) void dw_v2(
    const float* __restrict__ inb, float* __restrict__ outb,
    long iz, long ib,
    const float* __restrict__ w27b, const float* __restrict__ biasb, int blk0)
{
    __shared__ float sp[16 * 324];
    const int tid = threadIdx.x;
    const int x = tid & 15, y = tid >> 4;
    const int c = blockIdx.x, b = blockIdx.y, z = blockIdx.z;
    const int blk = blk0 + z;

    const float* in = inb + (long)z * iz + (long)b * ib + (long)c * Lsp;
    float* out = outb + (long)z * iz + (long)b * ib + (long)c * Lsp;
    const float* wv = w27b + (long)blk * Cch * 27 + c * 27;
    const float bias = biasb[blk * Cch + c];

    for (int idx = tid; idx < 16 * 324; idx += 256) sp[idx] = 0.f;
    __syncthreads();
    for (int idx = tid; idx < 4096; idx += 256) {
        int zz = idx >> 8, rem = idx & 255;
        sp[zz * 324 + ((rem >> 4) + 1) * 18 + (rem & 15) + 1] = in[idx];
    }
    float w[27];
#pragma unroll
    for (int k = 0; k < 27; k++) w[k] = wv[k];
    __syncthreads();

    float p0[9], p1[9], p2[9];
#pragma unroll
    for (int k = 0; k < 9; k++) p0[k] = 0.f;
#pragma unroll
    for (int dy = 0; dy < 3; dy++)
#pragma unroll
        for (int dx = 0; dx < 3; dx++)
            p1[dy * 3 + dx] = sp[(y + dy) * 18 + (x + dx)];

#pragma unroll
    for (int zz = 0; zz < 16; zz++) {
        if (zz < 15) {
#pragma unroll
            for (int dy = 0; dy < 3; dy++)
#pragma unroll
                for (int dx = 0; dx < 3; dx++)
                    p2[dy * 3 + dx] = sp[(zz + 1) * 324 + (y + dy) * 18 + (x + dx)];
        } else {
#pragma unroll
            for (int k = 0; k < 9; k++) p2[k] = 0.f;
        }
        float a = bias;
#pragma unroll
        for (int k = 0; k < 9; k++) a += p0[k] * w[k];
#pragma unroll
        for (int k = 0; k < 9; k++) a += p1[k] * w[9 + k];
#pragma unroll
        for (int k = 0; k < 9; k++) a += p2[k] * w[18 + k];
        out[zz * 256 + tid] = a;
#pragma unroll
        for (int k = 0; k < 9; k++) { p0[k] = p1[k]; p1[k] = p2[k]; }
    }
}

// ---------------------------------------------------------------------------
extern "C" void kernel_launch(void* const* d_in, const int* in_sizes, int n_in,
                              void* d_out, int out_size)
{
    const float* query = (const float*)d_in[0];
    const float* m0 = (const float*)d_in[1];
    const float* m1 = (const float*)d_in[2];
    const float* m2 = (const float*)d_in[3];
    const float* m3 = (const float*)d_in[4];
    const int*   mask  = (const int*)d_in[5];
    const float* pw1_w = (const float*)d_in[6];
    const float* pw1_b = (const float*)d_in[7];
    const float* ln1_g = (const float*)d_in[8];
    const float* ln1_b = (const float*)d_in[9];
    const float* dw_w  = (const float*)d_in[10];
    const float* dw_b  = (const float*)d_in[11];
    const float* ln2_g = (const float*)d_in[12];
    const float* ln2_b = (const float*)d_in[13];
    const float* pw2_w = (const float*)d_in[14];
    const float* pw2_b = (const float*)d_in[15];
    const float* ln3_g = (const float*)d_in[16];
    const float* ln3_b = (const float*)d_in[17];
    float* out = (float*)d_out;

    float *y1, *y2, *qb, *kv, *xb, *at, *atp;
    cudaGetSymbolAddress((void**)&y1, g_y1);
    cudaGetSymbolAddress((void**)&y2, g_y2);
    cudaGetSymbolAddress((void**)&qb, g_q);
    cudaGetSymbolAddress((void**)&kv, g_KV);
    cudaGetSymbolAddress((void**)&xb, g_x);
    cudaGetSymbolAddress((void**)&at, g_at);
    cudaGetSymbolAddress((void**)&atp, g_atp);
    float* Kb = kv;
    float* Vb = kv + (long)Bb * C4L;

    cudaFuncSetAttribute(pw_v6, cudaFuncAttributeMaxDynamicSharedMemorySize, PW_SMEM);
    cudaFuncSetAttribute(qk_v6, cudaFuncAttributeMaxDynamicSharedMemorySize, QK_SMEM);
    cudaFuncSetAttribute(av_mma, cudaFuncAttributeMaxDynamicSharedMemorySize, AV_SMEM);

    const long S2 = 4L * BCL, S1 = BCL, S0 = CL;
    const dim3 pw1_grid(32, Bb, 1);
    const dim3 pw8_grid(32, Bb, 8);

    // ---- query block (blk 0) ----
    pw_v6<<<pw1_grid, 512, PW_SMEM>>>(query, query, query, query, 0, 0, 0, CL,
        pw1_w, pw1_b, ln1_g, ln1_b, ln1_g, ln1_b, 0,
        nullptr, 0, y1, S2, S1, S0, 2);
    dw_v2<<<dim3(Cch, Bb, 1), 256>>>(y1, y2, BCL, CL, dw_w, dw_b, 0);
    pw_v6<<<pw1_grid, 512, PW_SMEM>>>(y2, y2, y2, y2, 0, S2, S1, S0,
        pw2_w, pw2_b, ln2_g, ln2_b, ln3_g, ln3_b, 0,
        nullptr, 0, qb, 0, 0, CL, 1);

    // ---- K/V blocks (blk 1..8), batched over grid.z ----
    pw_v6<<<pw8_grid, 512, PW_SMEM>>>(m0, m1, m2, m3, 1, 0, 0, CL,
        pw1_w, pw1_b, ln1_g, ln1_b, ln1_g, ln1_b, 1,
        nullptr, 0, y1, S2, S1, S0, 2);
    dw_v2<<<dim3(Cch, Bb, 8), 256>>>(y1, y2, BCL, CL, dw_w, dw_b, 1);
    pw_v6<<<pw8_grid, 512, PW_SMEM>>>(y2, y2, y2, y2, 0, S2, S1, S0,
        pw2_w, pw2_b, ln2_g, ln2_b, ln3_g, ln3_b, 1,
        nullptr, 0, kv, (long)Bb * C4L, CL, C4L, 1);

    // ---- attention ----
    qk_v6<<<dim3(4, 4, Bb), 512, QK_SMEM>>>(qb, Kb, atp);
    softmax_v6<<<Bb * 128, 128>>>(atp, at, mask);
    av_mma<<<dim3(32, Bb), 256, AV_SMEM>>>(at, Vb, xb);

    // ---- out_project (blk 9) + residual ----
    pw_v6<<<pw1_grid, 512, PW_SMEM>>>(xb, xb, xb, xb, 0, 0, 0, CL,
        pw1_w, pw1_b, ln1_g, ln1_b, ln1_g, ln1_b, 9,
        nullptr, 0, y1, S2, S1, S0, 2);
    dw_v2<<<dim3(Cch, Bb, 1), 256>>>(y1, y2, BCL, CL, dw_w, dw_b, 9);
    pw_v6<<<pw1_grid, 512, PW_SMEM>>>(y2, y2, y2, y2, 0, S2, S1, S0,
        pw2_w, pw2_b, ln2_g, ln2_b, ln3_g, ln3_b, 9,
        query, CL, out, 0, 0, CL, 1 | 4);
}

// round 7
// speedup vs baseline: 2.6236x; 1.1179x over previous
#include <cuda_runtime.h>
#include <math.h>
#include <stdint.h>

#define Bb   8
#define Cch  128
#define Lsp  4096
#define CL   (Cch*Lsp)        // 524288
#define C4L  (4*CL)
#define BCL  (Bb*CL)

// ---------------- scratch (static device memory) ----------------------------
__device__ float g_y1[9*BCL];
__device__ float g_y2[9*BCL];
__device__ float g_q [BCL];
__device__ float g_KV[2*Bb*C4L];
__device__ float g_x [BCL];
__device__ float g_at [Bb*128*512];      // final softmax probs
__device__ float g_atp[4*Bb*128*512];    // qk partials (4 L-parts)

__device__ __forceinline__ float gelu_exact(float x) {
    return 0.5f * x * (1.0f + erff(x * 0.70710678118654752f));
}

// ======================= bf16 hi/lo split-pack ==============================
// pack two floats (x0 = even/lower k, x1 = odd/upper k) into:
//   h = bf16x2{lo=bf(x0), hi=bf(x1)},  l = bf16x2 of the residuals
__device__ __forceinline__ void packbf2(float x0, float x1, uint32_t& h, uint32_t& l) {
    asm("cvt.rn.bf16x2.f32 %0, %1, %2;" : "=r"(h) : "f"(x1), "f"(x0));
    float h0 = __uint_as_float(h << 16);
    float h1 = __uint_as_float(h & 0xffff0000u);
    asm("cvt.rn.bf16x2.f32 %0, %1, %2;" : "=r"(l) : "f"(x1 - h1), "f"(x0 - h0));
}

// D(16x8) += A(16x16) * B(16x8), bf16 inputs, fp32 accum
__device__ __forceinline__ void mmabf(float* d,
    uint32_t a0, uint32_t a1, uint32_t a2, uint32_t a3, uint32_t b0, uint32_t b1)
{
    asm volatile(
        "mma.sync.aligned.m16n8k16.row.col.f32.bf16.bf16.f32 "
        "{%0,%1,%2,%3}, {%4,%5,%6,%7}, {%8,%9}, {%0,%1,%2,%3};"
        : "+f"(d[0]), "+f"(d[1]), "+f"(d[2]), "+f"(d[3])
        : "r"(a0), "r"(a1), "r"(a2), "r"(a3), "r"(b0), "r"(b1));
}
__device__ __forceinline__ void mma3bf(float* d,
    const uint32_t* ah, const uint32_t* al,
    uint32_t bh0, uint32_t bh1, uint32_t bl0, uint32_t bl1)
{
    mmabf(d, ah[0], ah[1], ah[2], ah[3], bl0, bl1);
    mmabf(d, al[0], al[1], al[2], al[3], bh0, bh1);
    mmabf(d, ah[0], ah[1], ah[2], ah[3], bh0, bh1);
}

// ---- tf32 helpers (av kernel) ----------------------------------------------
__device__ __forceinline__ void mma8(float* d,
    uint32_t a0, uint32_t a1, uint32_t a2, uint32_t a3, uint32_t b0, uint32_t b1)
{
    asm volatile(
        "mma.sync.aligned.m16n8k8.row.col.f32.tf32.tf32.f32 "
        "{%0,%1,%2,%3}, {%4,%5,%6,%7}, {%8,%9}, {%0,%1,%2,%3};"
        : "+f"(d[0]), "+f"(d[1]), "+f"(d[2]), "+f"(d[3])
        : "r"(a0), "r"(a1), "r"(a2), "r"(a3), "r"(b0), "r"(b1));
}
__device__ __forceinline__ uint32_t tf32r(float x) {
    uint32_t r; asm("cvt.rna.tf32.f32 %0, %1;" : "=r"(r) : "f"(x)); return r;
}
__device__ __forceinline__ void split32(float x, uint32_t& h, uint32_t& l) {
    h = tf32r(x); l = tf32r(x - __uint_as_float(h));
}
__device__ __forceinline__ void mma3(float* d,
    const uint32_t* ah, const uint32_t* al,
    uint32_t bh0, uint32_t bh1, uint32_t bl0, uint32_t bl1)
{
    mma8(d, ah[0], ah[1], ah[2], ah[3], bl0, bl1);
    mma8(d, al[0], al[1], al[2], al[3], bh0, bh1);
    mma8(d, ah[0], ah[1], ah[2], ah[3], bh0, bh1);
}

// ---------------------------------------------------------------------------
// Fused pointwise block, split-array bf16 mma. 512 threads, 16 warps.
// imode: 0: inq + b*CL | 1: (z==0?inq:mods[(z-1)&3]) + b*CL | 2: inq + z*BCL + b*CL
// omode: 0: out0 + b*CL | 1: out0 + z*BCL + b*CL | 2: z==0 -> out0+b*CL, else KV layout
// flags: bit0 in LN+GELU, bit1 out GELU, bit2 residual
// ---------------------------------------------------------------------------
#define NW 68
#define CS_STR 132
#define PW_SMEM ((4*128*NW + 1024 + 384) * 4)

__global__ __launch_bounds__(512) void pw_v7(
    const float* __restrict__ inq,
    const float* __restrict__ mm0, const float* __restrict__ mm1,
    const float* __restrict__ mm2, const float* __restrict__ mm3,
    int imode,
    const float* __restrict__ Wb, const float* __restrict__ biasb,
    const float* __restrict__ g1b, const float* __restrict__ b1b,
    const float* __restrict__ g2b, const float* __restrict__ b2b,
    int blk0,
    const float* __restrict__ res,
    float* __restrict__ out0, float* __restrict__ out1, int omode,
    int flags)
{
    extern __shared__ uint32_t smu[];
    uint32_t* Ah = smu;
    uint32_t* Al = smu + 128 * NW;
    uint32_t* Wh = smu + 2 * 128 * NW;
    uint32_t* Wl = smu + 3 * 128 * NW;
    float* red = (float*)(smu + 4 * 128 * NW);   // [2][4][128]
    float* ps  = red + 1024;                     // bias | go | bo
    float* Cs  = (float*)smu;                    // epilogue alias (Ah+Al region)

    const int tid = threadIdx.x;
    const int lane = tid & 31, wid = tid >> 5;
    const int gid = lane >> 2, tig = lane & 3;
    const int t = tid & 127, p = tid >> 7;
    const int cb = p * 32;
    const int b = blockIdx.y, z = blockIdx.z;
    const int l0 = blockIdx.x * 128;
    const int blk = blk0 + z;

    const float* src;
    if (imode == 0) src = inq;
    else if (imode == 1) {
        if (z == 0) src = inq;
        else { int zs = (z - 1) & 3; src = zs == 0 ? mm0 : zs == 1 ? mm1 : zs == 2 ? mm2 : mm3; }
    } else src = inq + (long)z * BCL;
    const float* inp = src + (long)b * CL + l0;

    float* outp;
    if (omode == 0) outp = out0 + (long)b * CL + l0;
    else if (omode == 1) outp = out0 + (long)z * BCL + (long)b * CL + l0;
    else {
        if (z == 0) outp = out0 + (long)b * CL + l0;
        else {
            int z1 = z - 1;
            outp = out1 + (long)(z1 >> 2) * ((long)Bb * C4L)
                 + (long)(z1 & 3) * CL + (long)b * C4L + l0;
        }
    }

    const float* W    = Wb + (long)blk * 128 * 128;
    const float* bias = biasb + blk * 128;
    const float* gi = g1b + blk * 128, *bi = b1b + blk * 128;
    const float* go = g2b + blk * 128, *bo = b2b + blk * 128;

    // ---- A loads: 4 threads per token, 32 channels each (coalesced) ----
    float v[32];
    float s = 0.f, q = 0.f;
#pragma unroll
    for (int i = 0; i < 32; i++) {
        v[i] = inp[(long)(cb + i) * Lsp + t];
        s += v[i]; q += v[i] * v[i];
    }
    // ---- W staging: float4 -> split bf16x2 pairs ----
#pragma unroll
    for (int j = 0; j < 8; j++) {
        int idx = tid + j * 512;
        int o = idx >> 5, c4 = idx & 31;
        float4 w = *(const float4*)&W[o * 128 + c4 * 4];
        uint32_t h0, l0w, h1, l1w;
        packbf2(w.x, w.y, h0, l0w);
        packbf2(w.z, w.w, h1, l1w);
        *(uint2*)&Wh[o * NW + c4 * 2] = make_uint2(h0, h1);
        *(uint2*)&Wl[o * NW + c4 * 2] = make_uint2(l0w, l1w);
    }
    if (tid < 128) { ps[tid] = bias[tid]; ps[128 + tid] = go[tid]; ps[256 + tid] = bo[tid]; }

    if (flags & 1) {
        red[p * 128 + t] = s; red[512 + p * 128 + t] = q;
        __syncthreads();
        float S = red[t] + red[128 + t] + red[256 + t] + red[384 + t];
        float Q = red[512 + t] + red[640 + t] + red[768 + t] + red[896 + t];
        float mean = S * (1.f / 128.f);
        float rstd = rsqrtf(Q * (1.f / 128.f) - mean * mean + 1e-6f);
#pragma unroll
        for (int i = 0; i < 16; i++) {
            float x0 = gelu_exact((v[2*i]   - mean) * rstd * gi[cb + 2*i]   + bi[cb + 2*i]);
            float x1 = gelu_exact((v[2*i+1] - mean) * rstd * gi[cb + 2*i+1] + bi[cb + 2*i+1]);
            uint32_t h, l;
            packbf2(x0, x1, h, l);
            Ah[t * NW + cb / 2 + i] = h;
            Al[t * NW + cb / 2 + i] = l;
        }
    } else {
#pragma unroll
        for (int i = 0; i < 16; i++) {
            uint32_t h, l;
            packbf2(v[2*i], v[2*i+1], h, l);
            Ah[t * NW + cb / 2 + i] = h;
            Al[t * NW + cb / 2 + i] = l;
        }
    }
    __syncthreads();

    // ---- mainloop: warp tile m32 x n32, k16 steps, zero PRMT ----
    const int m0b = (wid >> 2) * 32, n0b = (wid & 3) * 32;
    float acc[8][4];
#pragma unroll
    for (int i = 0; i < 8; i++)
#pragma unroll
        for (int j = 0; j < 4; j++) acc[i][j] = 0.f;

#pragma unroll
    for (int k0 = 0; k0 < 128; k0 += 16) {
        const int kw = k0 / 2 + tig;
        uint32_t bh[4][2], bl[4][2];
#pragma unroll
        for (int nt = 0; nt < 4; nt++) {
            int n = n0b + nt * 8 + gid;
            bh[nt][0] = Wh[n * NW + kw];     bh[nt][1] = Wh[n * NW + kw + 4];
            bl[nt][0] = Wl[n * NW + kw];     bl[nt][1] = Wl[n * NW + kw + 4];
        }
#pragma unroll
        for (int mt = 0; mt < 2; mt++) {
            int r0 = m0b + mt * 16 + gid, r1 = r0 + 8;
            uint32_t ah[4], al[4];
            ah[0] = Ah[r0 * NW + kw];     ah[1] = Ah[r1 * NW + kw];
            ah[2] = Ah[r0 * NW + kw + 4]; ah[3] = Ah[r1 * NW + kw + 4];
            al[0] = Al[r0 * NW + kw];     al[1] = Al[r1 * NW + kw];
            al[2] = Al[r0 * NW + kw + 4]; al[3] = Al[r1 * NW + kw + 4];
#pragma unroll
            for (int nt = 0; nt < 4; nt++)
                mma3bf(acc[mt * 4 + nt], ah, al,
                       bh[nt][0], bh[nt][1], bl[nt][0], bl[nt][1]);
        }
    }
    __syncthreads();

    // ---- C -> smem (alias A region) ----
#pragma unroll
    for (int mt = 0; mt < 2; mt++)
#pragma unroll
        for (int nt = 0; nt < 4; nt++) {
            int m = m0b + mt * 16 + gid, n = n0b + nt * 8 + tig * 2;
            float* a = acc[mt * 4 + nt];
            *(float2*)&Cs[m * CS_STR + n] = make_float2(a[0], a[1]);
            *(float2*)&Cs[(m + 8) * CS_STR + n] = make_float2(a[2], a[3]);
        }
    __syncthreads();

    // ---- epilogue: +bias -> LN -> [GELU] -> [res] ----
    float w2[32];
    float s2 = 0.f, q2 = 0.f;
#pragma unroll
    for (int i = 0; i < 32; i++) {
        w2[i] = Cs[t * CS_STR + cb + i] + ps[cb + i];
        s2 += w2[i]; q2 += w2[i] * w2[i];
    }
    red[p * 128 + t] = s2; red[512 + p * 128 + t] = q2;
    __syncthreads();
    float S2 = red[t] + red[128 + t] + red[256 + t] + red[384 + t];
    float Q2 = red[512 + t] + red[640 + t] + red[768 + t] + red[896 + t];
    float mean2 = S2 * (1.f / 128.f);
    float rstd2 = rsqrtf(Q2 * (1.f / 128.f) - mean2 * mean2 + 1e-6f);
    const float* resp = (flags & 4) ? (res + (long)b * CL + l0) : nullptr;
#pragma unroll
    for (int i = 0; i < 32; i++) {
        int c = cb + i;
        float val = (w2[i] - mean2) * rstd2 * ps[128 + c] + ps[256 + c];
        if (flags & 2) val = gelu_exact(val);
        if (flags & 4) val += resp[(long)c * Lsp + t];
        outp[(long)c * Lsp + t] = val;
    }
}

// ---------------------------------------------------------------------------
// qk partial: atp[lp][b][c][kt+n] = sum over L-part of q[c,l]*K[k,l]
// split-array bf16 mma, 512 threads, grid (4 kt, 4 lp, 8 b)
// ---------------------------------------------------------------------------
#define QK_SMEM (4*128*NW*4)
__global__ __launch_bounds__(512) void qk_v7(
    const float* __restrict__ q, const float* __restrict__ K,
    float* __restrict__ atp)
{
    extern __shared__ uint32_t smu[];
    uint32_t* Qh = smu;
    uint32_t* Ql = smu + 128 * NW;
    uint32_t* Kh = smu + 2 * 128 * NW;
    uint32_t* Kl = smu + 3 * 128 * NW;
    const int tid = threadIdx.x;
    const int lane = tid & 31, wid = tid >> 5;
    const int gid = lane >> 2, tig = lane & 3;
    const int kt = blockIdx.x * 128, lp = blockIdx.y, b = blockIdx.z;
    const float* qp = q + (long)b * CL;
    const float* Kp = K + (long)b * C4L + (long)kt * Lsp;
    const int lbase = lp * 1024;

    const int m0b = (wid >> 2) * 32, n0b = (wid & 3) * 32;
    float acc[8][4];
#pragma unroll
    for (int i = 0; i < 8; i++)
#pragma unroll
        for (int j = 0; j < 4; j++) acc[i][j] = 0.f;

    for (int lc = 0; lc < 1024; lc += 128) {
        const int l0 = lbase + lc;
        __syncthreads();
#pragma unroll
        for (int j = 0; j < 8; j++) {
            int idx = tid + j * 512;
            int r = idx >> 5, c4 = idx & 31;
            float4 a = *(const float4*)&qp[(long)r * Lsp + l0 + c4 * 4];
            uint32_t h0, l0w, h1, l1w;
            packbf2(a.x, a.y, h0, l0w); packbf2(a.z, a.w, h1, l1w);
            *(uint2*)&Qh[r * NW + c4 * 2] = make_uint2(h0, h1);
            *(uint2*)&Ql[r * NW + c4 * 2] = make_uint2(l0w, l1w);
            float4 kk = *(const float4*)&Kp[(long)r * Lsp + l0 + c4 * 4];
            packbf2(kk.x, kk.y, h0, l0w); packbf2(kk.z, kk.w, h1, l1w);
            *(uint2*)&Kh[r * NW + c4 * 2] = make_uint2(h0, h1);
            *(uint2*)&Kl[r * NW + c4 * 2] = make_uint2(l0w, l1w);
        }
        __syncthreads();
#pragma unroll
        for (int k0 = 0; k0 < 128; k0 += 16) {
            const int kw = k0 / 2 + tig;
            uint32_t bh[4][2], bl[4][2];
#pragma unroll
            for (int nt = 0; nt < 4; nt++) {
                int n = n0b + nt * 8 + gid;
                bh[nt][0] = Kh[n * NW + kw];     bh[nt][1] = Kh[n * NW + kw + 4];
                bl[nt][0] = Kl[n * NW + kw];     bl[nt][1] = Kl[n * NW + kw + 4];
            }
#pragma unroll
            for (int mt = 0; mt < 2; mt++) {
                int r0 = m0b + mt * 16 + gid, r1 = r0 + 8;
                uint32_t ah[4], al[4];
                ah[0] = Qh[r0 * NW + kw];     ah[1] = Qh[r1 * NW + kw];
                ah[2] = Qh[r0 * NW + kw + 4]; ah[3] = Qh[r1 * NW + kw + 4];
                al[0] = Ql[r0 * NW + kw];     al[1] = Ql[r1 * NW + kw];
                al[2] = Ql[r0 * NW + kw + 4]; al[3] = Ql[r1 * NW + kw + 4];
#pragma unroll
                for (int nt = 0; nt < 4; nt++)
                    mma3bf(acc[mt * 4 + nt], ah, al,
                           bh[nt][0], bh[nt][1], bl[nt][0], bl[nt][1]);
            }
        }
    }
    float* ap = atp + (long)lp * (Bb * 65536) + (long)b * 65536;
#pragma unroll
    for (int mt = 0; mt < 2; mt++)
#pragma unroll
        for (int nt = 0; nt < 4; nt++) {
            int m = m0b + mt * 16 + gid;
            int n = kt + n0b + nt * 8 + tig * 2;
            float* a = acc[mt * 4 + nt];
            *(float2*)&ap[(long)m * 512 + n] = make_float2(a[0], a[1]);
            *(float2*)&ap[(long)(m + 8) * 512 + n] = make_float2(a[2], a[3]);
        }
}

// ---------------------------------------------------------------------------
// masked softmax: sums 4 qk partials, scales by 1/64, writes probs
// ---------------------------------------------------------------------------
__global__ __launch_bounds__(128) void softmax_v6(
    const float* __restrict__ atp, float* __restrict__ at,
    const int* __restrict__ mask)
{
    __shared__ float sm[128];
    const int row = blockIdx.x;
    const int b = row >> 7;
    const int t = threadIdx.x;
    const float sc = 0.015625f;
    const long roff = (long)row * 512;
    const long pstr = (long)Bb * 65536;

    float v[4];
    float mx = -INFINITY;
#pragma unroll
    for (int j = 0; j < 4; j++) {
        bool on = mask[b * 4 + j] > 0;
        float sum = atp[roff + j * 128 + t] + atp[pstr + roff + j * 128 + t]
                  + atp[2 * pstr + roff + j * 128 + t] + atp[3 * pstr + roff + j * 128 + t];
        v[j] = on ? sum * sc : -INFINITY;
        mx = fmaxf(mx, v[j]);
    }
    sm[t] = mx; __syncthreads();
    for (int s = 64; s > 0; s >>= 1) {
        if (t < s) sm[t] = fmaxf(sm[t], sm[t + s]);
        __syncthreads();
    }
    mx = sm[0]; __syncthreads();

    float sum = 0.f;
#pragma unroll
    for (int j = 0; j < 4; j++) {
        v[j] = (v[j] == -INFINITY) ? 0.f : expf(v[j] - mx);
        sum += v[j];
    }
    sm[t] = sum; __syncthreads();
    for (int s = 64; s > 0; s >>= 1) {
        if (t < s) sm[t] += sm[t + s];
        __syncthreads();
    }
    float inv = 1.f / sm[0];
#pragma unroll
    for (int j = 0; j < 4; j++) at[roff + j * 128 + t] = v[j] * inv;
}

// ---------------------------------------------------------------------------
// av: x[b,c,lt+n] = sum_k attn[b,c,k] V[b,k,lt+n]  (3xTF32)
// ---------------------------------------------------------------------------
#define AV_SMEM ((128*68 + 64*136) * 4)
__global__ __launch_bounds__(256) void av_mma(
    const float* __restrict__ at, const float* __restrict__ V,
    float* __restrict__ xout)
{
    extern __shared__ float sm[];
    float* Aa = sm;                  // [128][68]
    float* Vs = sm + 128 * 68;       // [64][136]
    const int tid = threadIdx.x;
    const int lane = tid & 31, wid = tid >> 5;
    const int gid = lane >> 2, tig = lane & 3;
    const int lt = blockIdx.x * 128;
    const int b = blockIdx.y;
    const float* ap = at + (long)b * 65536;
    const float* Vp = V + (long)b * C4L;

    const int wm = wid >> 2, wn = wid & 3;
    const int m0b = wm * 64, n0b = wn * 32;
    float acc[16][4];
#pragma unroll
    for (int i = 0; i < 16; i++)
#pragma unroll
        for (int j = 0; j < 4; j++) acc[i][j] = 0.f;

    for (int kg = 0; kg < 512; kg += 64) {
        __syncthreads();
#pragma unroll 4
        for (int i = 0; i < 8; i++) {
            int idx = tid + i * 256;
            int r = idx >> 4, c4 = idx & 15;
            *(float4*)&Aa[r * 68 + c4 * 4] = *(const float4*)&ap[(long)r * 512 + kg + c4 * 4];
        }
#pragma unroll 4
        for (int i = 0; i < 8; i++) {
            int idx = tid + i * 256;
            int r = idx >> 5, c4 = idx & 31;
            *(float4*)&Vs[r * 136 + c4 * 4] =
                *(const float4*)&Vp[(long)(kg + r) * Lsp + lt + c4 * 4];
        }
        __syncthreads();
        for (int k0 = 0; k0 < 64; k0 += 8) {
            uint32_t bh[4][2], bl[4][2];
#pragma unroll
            for (int nt = 0; nt < 4; nt++) {
                int n = n0b + nt * 8 + gid;
                split32(Vs[(k0 + tig) * 136 + n],     bh[nt][0], bl[nt][0]);
                split32(Vs[(k0 + tig + 4) * 136 + n], bh[nt][1], bl[nt][1]);
            }
#pragma unroll
            for (int mt = 0; mt < 4; mt++) {
                int m = m0b + mt * 16 + gid;
                uint32_t ah[4], al[4];
                split32(Aa[m * 68 + k0 + tig],           ah[0], al[0]);
                split32(Aa[(m + 8) * 68 + k0 + tig],     ah[1], al[1]);
                split32(Aa[m * 68 + k0 + tig + 4],       ah[2], al[2]);
                split32(Aa[(m + 8) * 68 + k0 + tig + 4], ah[3], al[3]);
#pragma unroll
                for (int nt = 0; nt < 4; nt++)
                    mma3(acc[mt * 4 + nt], ah, al,
                         bh[nt][0], bh[nt][1], bl[nt][0], bl[nt][1]);
            }
        }
    }
    float* xp = xout + (long)b * CL + lt;
#pragma unroll
    for (int mt = 0; mt < 4; mt++)
#pragma unroll
        for (int nt = 0; nt < 4; nt++) {
            int m = m0b + mt * 16 + gid;
            int n = n0b + nt * 8 + tig * 2;
            float* a = acc[mt * 4 + nt];
            *(float2*)&xp[(long)m * Lsp + n] = make_float2(a[0], a[1]);
            *(float2*)&xp[(long)(m + 8) * Lsp + n] = make_float2(a[2], a[3]);
        }
}

// ---------------------------------------------------------------------------
// Depthwise 3x3x3 + bias
// ---------------------------------------------------------------------------
__global__ __launch_bounds__(256) void dw_v2(
    const float* __restrict__ inb, float* __restrict__ outb,
    long iz, long ib,
    const float* __restrict__ w27b, const float* __restrict__ biasb, int blk0)
{
    __shared__ float sp[16 * 324];
    const int tid = threadIdx.x;
    const int x = tid & 15, y = tid >> 4;
    const int c = blockIdx.x, b = blockIdx.y, z = blockIdx.z;
    const int blk = blk0 + z;

    const float* in = inb + (long)z * iz + (long)b * ib + (long)c * Lsp;
    float* out = outb + (long)z * iz + (long)b * ib + (long)c * Lsp;
    const float* wv = w27b + (long)blk * Cch * 27 + c * 27;
    const float bias = biasb[blk * Cch + c];

    for (int idx = tid; idx < 16 * 324; idx += 256) sp[idx] = 0.f;
    __syncthreads();
    for (int idx = tid; idx < 4096; idx += 256) {
        int zz = idx >> 8, rem = idx & 255;
        sp[zz * 324 + ((rem >> 4) + 1) * 18 + (rem & 15) + 1] = in[idx];
    }
    float w[27];
#pragma unroll
    for (int k = 0; k < 27; k++) w[k] = wv[k];
    __syncthreads();

    float p0[9], p1[9], p2[9];
#pragma unroll
    for (int k = 0; k < 9; k++) p0[k] = 0.f;
#pragma unroll
    for (int dy = 0; dy < 3; dy++)
#pragma unroll
        for (int dx = 0; dx < 3; dx++)
            p1[dy * 3 + dx] = sp[(y + dy) * 18 + (x + dx)];

#pragma unroll
    for (int zz = 0; zz < 16; zz++) {
        if (zz < 15) {
#pragma unroll
            for (int dy = 0; dy < 3; dy++)
#pragma unroll
                for (int dx = 0; dx < 3; dx++)
                    p2[dy * 3 + dx] = sp[(zz + 1) * 324 + (y + dy) * 18 + (x + dx)];
        } else {
#pragma unroll
            for (int k = 0; k < 9; k++) p2[k] = 0.f;
        }
        float a = bias;
#pragma unroll
        for (int k = 0; k < 9; k++) a += p0[k] * w[k];
#pragma unroll
        for (int k = 0; k < 9; k++) a += p1[k] * w[9 + k];
#pragma unroll
        for (int k = 0; k < 9; k++) a += p2[k] * w[18 + k];
        out[zz * 256 + tid] = a;
#pragma unroll
        for (int k = 0; k < 9; k++) { p0[k] = p1[k]; p1[k] = p2[k]; }
    }
}

// ---------------------------------------------------------------------------
extern "C" void kernel_launch(void* const* d_in, const int* in_sizes, int n_in,
                              void* d_out, int out_size)
{
    const float* query = (const float*)d_in[0];
    const float* m0 = (const float*)d_in[1];
    const float* m1 = (const float*)d_in[2];
    const float* m2 = (const float*)d_in[3];
    const float* m3 = (const float*)d_in[4];
    const int*   mask  = (const int*)d_in[5];
    const float* pw1_w = (const float*)d_in[6];
    const float* pw1_b = (const float*)d_in[7];
    const float* ln1_g = (const float*)d_in[8];
    const float* ln1_b = (const float*)d_in[9];
    const float* dw_w  = (const float*)d_in[10];
    const float* dw_b  = (const float*)d_in[11];
    const float* ln2_g = (const float*)d_in[12];
    const float* ln2_b = (const float*)d_in[13];
    const float* pw2_w = (const float*)d_in[14];
    const float* pw2_b = (const float*)d_in[15];
    const float* ln3_g = (const float*)d_in[16];
    const float* ln3_b = (const float*)d_in[17];
    float* out = (float*)d_out;

    float *y1, *y2, *qb, *kv, *xb, *at, *atp;
    cudaGetSymbolAddress((void**)&y1, g_y1);
    cudaGetSymbolAddress((void**)&y2, g_y2);
    cudaGetSymbolAddress((void**)&qb, g_q);
    cudaGetSymbolAddress((void**)&kv, g_KV);
    cudaGetSymbolAddress((void**)&xb, g_x);
    cudaGetSymbolAddress((void**)&at, g_at);
    cudaGetSymbolAddress((void**)&atp, g_atp);
    float* Kb = kv;
    float* Vb = kv + (long)Bb * C4L;

    cudaFuncSetAttribute(pw_v7, cudaFuncAttributeMaxDynamicSharedMemorySize, PW_SMEM);
    cudaFuncSetAttribute(qk_v7, cudaFuncAttributeMaxDynamicSharedMemorySize, QK_SMEM);
    cudaFuncSetAttribute(av_mma, cudaFuncAttributeMaxDynamicSharedMemorySize, AV_SMEM);

    // ---- blocks 0..8 (query + K/V maps) in one chain of 3 launches ----
    pw_v7<<<dim3(32, Bb, 9), 512, PW_SMEM>>>(
        query, m0, m1, m2, m3, /*imode=*/1,
        pw1_w, pw1_b, ln1_g, ln1_b, ln1_g, ln1_b, /*blk0=*/0,
        nullptr, y1, nullptr, /*omode=*/1, /*flags=*/2);
    dw_v2<<<dim3(Cch, Bb, 9), 256>>>(y1, y2, BCL, CL, dw_w, dw_b, 0);
    pw_v7<<<dim3(32, Bb, 9), 512, PW_SMEM>>>(
        y2, nullptr, nullptr, nullptr, nullptr, /*imode=*/2,
        pw2_w, pw2_b, ln2_g, ln2_b, ln3_g, ln3_b, /*blk0=*/0,
        nullptr, qb, kv, /*omode=*/2, /*flags=*/1);

    // ---- attention ----
    qk_v7<<<dim3(4, 4, Bb), 512, QK_SMEM>>>(qb, Kb, atp);
    softmax_v6<<<Bb * 128, 128>>>(atp, at, mask);
    av_mma<<<dim3(32, Bb), 256, AV_SMEM>>>(at, Vb, xb);

    // ---- out_project (blk 9) + residual ----
    pw_v7<<<dim3(32, Bb, 1), 512, PW_SMEM>>>(
        xb, nullptr, nullptr, nullptr, nullptr, /*imode=*/0,
        pw1_w, pw1_b, ln1_g, ln1_b, ln1_g, ln1_b, /*blk0=*/9,
        nullptr, y1, nullptr, /*omode=*/0, /*flags=*/2);
    dw_v2<<<dim3(Cch, Bb, 1), 256>>>(y1, y2, BCL, CL, dw_w, dw_b, 9);
    pw_v7<<<dim3(32, Bb, 1), 512, PW_SMEM>>>(
        y2, nullptr, nullptr, nullptr, nullptr, /*imode=*/0,
        pw2_w, pw2_b, ln2_g, ln2_b, ln3_g, ln3_b, /*blk0=*/9,
        query, out, nullptr, /*omode=*/0, /*flags=*/1 | 4);
}

// round 8
// speedup vs baseline: 2.9744x; 1.1337x over previous
#include <cuda_runtime.h>
#include <math.h>
#include <stdint.h>

#define Bb   8
#define Cch  128
#define Lsp  4096
#define CL   (Cch*Lsp)        // 524288
#define C4L  (4*CL)
#define BCL  (Bb*CL)

// ---------------- scratch (static device memory) ----------------------------
__device__ float g_y1[9*BCL];
__device__ float g_y2[9*BCL];
__device__ float g_q [BCL];
__device__ float g_KV[2*Bb*C4L];
__device__ float g_x [BCL];
__device__ float g_at [Bb*128*512];      // final softmax probs
__device__ float g_atp[4*Bb*128*512];    // qk partials (4 L-parts)

__device__ __forceinline__ float gelu_exact(float x) {
    return 0.5f * x * (1.0f + erff(x * 0.70710678118654752f));
}

// ======================= bf16 hi/lo split-pack ==============================
__device__ __forceinline__ void packbf2(float x0, float x1, uint32_t& h, uint32_t& l) {
    asm("cvt.rn.bf16x2.f32 %0, %1, %2;" : "=r"(h) : "f"(x1), "f"(x0));
    float h0 = __uint_as_float(h << 16);
    float h1 = __uint_as_float(h & 0xffff0000u);
    asm("cvt.rn.bf16x2.f32 %0, %1, %2;" : "=r"(l) : "f"(x1 - h1), "f"(x0 - h0));
}

__device__ __forceinline__ void mmabf(float* d,
    uint32_t a0, uint32_t a1, uint32_t a2, uint32_t a3, uint32_t b0, uint32_t b1)
{
    asm volatile(
        "mma.sync.aligned.m16n8k16.row.col.f32.bf16.bf16.f32 "
        "{%0,%1,%2,%3}, {%4,%5,%6,%7}, {%8,%9}, {%0,%1,%2,%3};"
        : "+f"(d[0]), "+f"(d[1]), "+f"(d[2]), "+f"(d[3])
        : "r"(a0), "r"(a1), "r"(a2), "r"(a3), "r"(b0), "r"(b1));
}
__device__ __forceinline__ void mma3bf(float* d,
    const uint32_t* ah, const uint32_t* al,
    uint32_t bh0, uint32_t bh1, uint32_t bl0, uint32_t bl1)
{
    mmabf(d, ah[0], ah[1], ah[2], ah[3], bl0, bl1);
    mmabf(d, al[0], al[1], al[2], al[3], bh0, bh1);
    mmabf(d, ah[0], ah[1], ah[2], ah[3], bh0, bh1);
}

// ---- tf32 helpers (av kernel) ----------------------------------------------
__device__ __forceinline__ void mma8(float* d,
    uint32_t a0, uint32_t a1, uint32_t a2, uint32_t a3, uint32_t b0, uint32_t b1)
{
    asm volatile(
        "mma.sync.aligned.m16n8k8.row.col.f32.tf32.tf32.f32 "
        "{%0,%1,%2,%3}, {%4,%5,%6,%7}, {%8,%9}, {%0,%1,%2,%3};"
        : "+f"(d[0]), "+f"(d[1]), "+f"(d[2]), "+f"(d[3])
        : "r"(a0), "r"(a1), "r"(a2), "r"(a3), "r"(b0), "r"(b1));
}
__device__ __forceinline__ uint32_t tf32r(float x) {
    uint32_t r; asm("cvt.rna.tf32.f32 %0, %1;" : "=r"(r) : "f"(x)); return r;
}
__device__ __forceinline__ void split32(float x, uint32_t& h, uint32_t& l) {
    h = tf32r(x); l = tf32r(x - __uint_as_float(h));
}
__device__ __forceinline__ void mma3(float* d,
    const uint32_t* ah, const uint32_t* al,
    uint32_t bh0, uint32_t bh1, uint32_t bl0, uint32_t bl1)
{
    mma8(d, ah[0], ah[1], ah[2], ah[3], bl0, bl1);
    mma8(d, al[0], al[1], al[2], al[3], bh0, bh1);
    mma8(d, ah[0], ah[1], ah[2], ah[3], bh0, bh1);
}

// ---------------------------------------------------------------------------
// Fused pointwise block: 64-token x 128-out tile, 256 threads, 2 CTAs/SM.
// imode: 0 inq+b*CL | 1 (z==0?inq:mods[(z-1)&3])+b*CL | 2 inq+z*BCL+b*CL
// omode: 0 out0+b*CL | 1 out0+z*BCL+b*CL | 2 z==0->out0, else KV layout
// flags: bit0 in LN+GELU, bit1 out GELU, bit2 residual
// ---------------------------------------------------------------------------
#define NW 68
#define AW (64*NW)      // 4352 words per A array
#define WW (128*NW)     // 8704 words per W array
#define CS_STR 132
#define PW_SMEM ((2*AW + 2*WW + 512 + 384) * 4)   // 108032 B

__global__ __launch_bounds__(256, 2) void pw_v8(
    const float* __restrict__ inq,
    const float* __restrict__ mm0, const float* __restrict__ mm1,
    const float* __restrict__ mm2, const float* __restrict__ mm3,
    int imode,
    const float* __restrict__ Wb, const float* __restrict__ biasb,
    const float* __restrict__ g1b, const float* __restrict__ b1b,
    const float* __restrict__ g2b, const float* __restrict__ b2b,
    int blk0,
    const float* __restrict__ res,
    float* __restrict__ out0, float* __restrict__ out1, int omode,
    int flags)
{
    extern __shared__ uint32_t smu[];
    uint32_t* Ah = smu;                // [64][NW]
    uint32_t* Al = smu + AW;
    uint32_t* Wh = smu + 2 * AW;       // [128][NW]
    uint32_t* Wl = smu + 2 * AW + WW;
    float* red = (float*)(smu + 2 * AW + 2 * WW);   // [2][4][64]
    float* ps  = red + 512;                          // bias | go | bo
    float* Cs  = (float*)smu;                        // epilogue alias (A region)

    const int tid = threadIdx.x;
    const int lane = tid & 31, wid = tid >> 5;
    const int gid = lane >> 2, tig = lane & 3;
    const int t = tid & 63, p = tid >> 6;       // token, channel-quarter
    const int cb = p * 32;
    const int b = blockIdx.y, z = blockIdx.z;
    const int l0 = blockIdx.x * 64;
    const int blk = blk0 + z;

    const float* src;
    if (imode == 0) src = inq;
    else if (imode == 1) {
        if (z == 0) src = inq;
        else { int zs = (z - 1) & 3; src = zs == 0 ? mm0 : zs == 1 ? mm1 : zs == 2 ? mm2 : mm3; }
    } else src = inq + (long)z * BCL;
    const float* inp = src + (long)b * CL + l0;

    float* outp;
    if (omode == 0) outp = out0 + (long)b * CL + l0;
    else if (omode == 1) outp = out0 + (long)z * BCL + (long)b * CL + l0;
    else {
        if (z == 0) outp = out0 + (long)b * CL + l0;
        else {
            int z1 = z - 1;
            outp = out1 + (long)(z1 >> 2) * ((long)Bb * C4L)
                 + (long)(z1 & 3) * CL + (long)b * C4L + l0;
        }
    }

    const float* W    = Wb + (long)blk * 128 * 128;
    const float* bias = biasb + blk * 128;
    const float* gi = g1b + blk * 128, *bi = b1b + blk * 128;
    const float* go = g2b + blk * 128, *bo = b2b + blk * 128;

    // ---- A loads: 4 threads per token, 32 channels each ----
    float v[32];
    float s = 0.f, q = 0.f;
#pragma unroll
    for (int i = 0; i < 32; i++) {
        v[i] = inp[(long)(cb + i) * Lsp + t];
        s += v[i]; q += v[i] * v[i];
    }
    // ---- W staging: float4 -> split bf16x2 pairs ----
#pragma unroll
    for (int j = 0; j < 16; j++) {
        int idx = tid + j * 256;
        int o = idx >> 5, c4 = idx & 31;
        float4 w = *(const float4*)&W[o * 128 + c4 * 4];
        uint32_t h0, l0w, h1, l1w;
        packbf2(w.x, w.y, h0, l0w);
        packbf2(w.z, w.w, h1, l1w);
        *(uint2*)&Wh[o * NW + c4 * 2] = make_uint2(h0, h1);
        *(uint2*)&Wl[o * NW + c4 * 2] = make_uint2(l0w, l1w);
    }
    if (tid < 128) { ps[tid] = bias[tid]; ps[128 + tid] = go[tid]; ps[256 + tid] = bo[tid]; }

    if (flags & 1) {
        red[p * 64 + t] = s; red[256 + p * 64 + t] = q;
        __syncthreads();
        float S = red[t] + red[64 + t] + red[128 + t] + red[192 + t];
        float Q = red[256 + t] + red[320 + t] + red[384 + t] + red[448 + t];
        float mean = S * (1.f / 128.f);
        float rstd = rsqrtf(Q * (1.f / 128.f) - mean * mean + 1e-6f);
#pragma unroll
        for (int i = 0; i < 16; i++) {
            float x0 = gelu_exact((v[2*i]   - mean) * rstd * gi[cb + 2*i]   + bi[cb + 2*i]);
            float x1 = gelu_exact((v[2*i+1] - mean) * rstd * gi[cb + 2*i+1] + bi[cb + 2*i+1]);
            uint32_t h, l;
            packbf2(x0, x1, h, l);
            Ah[t * NW + cb / 2 + i] = h;
            Al[t * NW + cb / 2 + i] = l;
        }
    } else {
#pragma unroll
        for (int i = 0; i < 16; i++) {
            uint32_t h, l;
            packbf2(v[2*i], v[2*i+1], h, l);
            Ah[t * NW + cb / 2 + i] = h;
            Al[t * NW + cb / 2 + i] = l;
        }
    }
    __syncthreads();

    // ---- mainloop: 8 warps (2m x 4n), warp tile m32 x n32 ----
    const int m0b = (wid >> 2) * 32, n0b = (wid & 3) * 32;
    float acc[8][4];
#pragma unroll
    for (int i = 0; i < 8; i++)
#pragma unroll
        for (int j = 0; j < 4; j++) acc[i][j] = 0.f;

#pragma unroll
    for (int k0 = 0; k0 < 128; k0 += 16) {
        const int kw = k0 / 2 + tig;
        uint32_t bh[4][2], bl[4][2];
#pragma unroll
        for (int nt = 0; nt < 4; nt++) {
            int n = n0b + nt * 8 + gid;
            bh[nt][0] = Wh[n * NW + kw];     bh[nt][1] = Wh[n * NW + kw + 4];
            bl[nt][0] = Wl[n * NW + kw];     bl[nt][1] = Wl[n * NW + kw + 4];
        }
#pragma unroll
        for (int mt = 0; mt < 2; mt++) {
            int r0 = m0b + mt * 16 + gid, r1 = r0 + 8;
            uint32_t ah[4], al[4];
            ah[0] = Ah[r0 * NW + kw];     ah[1] = Ah[r1 * NW + kw];
            ah[2] = Ah[r0 * NW + kw + 4]; ah[3] = Ah[r1 * NW + kw + 4];
            al[0] = Al[r0 * NW + kw];     al[1] = Al[r1 * NW + kw];
            al[2] = Al[r0 * NW + kw + 4]; al[3] = Al[r1 * NW + kw + 4];
#pragma unroll
            for (int nt = 0; nt < 4; nt++)
                mma3bf(acc[mt * 4 + nt], ah, al,
                       bh[nt][0], bh[nt][1], bl[nt][0], bl[nt][1]);
        }
    }
    __syncthreads();

    // ---- C -> smem (alias A region: 64 x CS_STR <= 2*AW) ----
#pragma unroll
    for (int mt = 0; mt < 2; mt++)
#pragma unroll
        for (int nt = 0; nt < 4; nt++) {
            int m = m0b + mt * 16 + gid, n = n0b + nt * 8 + tig * 2;
            float* a = acc[mt * 4 + nt];
            *(float2*)&Cs[m * CS_STR + n] = make_float2(a[0], a[1]);
            *(float2*)&Cs[(m + 8) * CS_STR + n] = make_float2(a[2], a[3]);
        }
    __syncthreads();

    // ---- epilogue: +bias -> LN -> [GELU] -> [res] ----
    float w2[32];
    float s2 = 0.f, q2 = 0.f;
#pragma unroll
    for (int i = 0; i < 32; i++) {
        w2[i] = Cs[t * CS_STR + cb + i] + ps[cb + i];
        s2 += w2[i]; q2 += w2[i] * w2[i];
    }
    red[p * 64 + t] = s2; red[256 + p * 64 + t] = q2;
    __syncthreads();
    float S2 = red[t] + red[64 + t] + red[128 + t] + red[192 + t];
    float Q2 = red[256 + t] + red[320 + t] + red[384 + t] + red[448 + t];
    float mean2 = S2 * (1.f / 128.f);
    float rstd2 = rsqrtf(Q2 * (1.f / 128.f) - mean2 * mean2 + 1e-6f);
    const float* resp = (flags & 4) ? (res + (long)b * CL + l0) : nullptr;
#pragma unroll
    for (int i = 0; i < 32; i++) {
        int c = cb + i;
        float val = (w2[i] - mean2) * rstd2 * ps[128 + c] + ps[256 + c];
        if (flags & 2) val = gelu_exact(val);
        if (flags & 4) val += resp[(long)c * Lsp + t];
        outp[(long)c * Lsp + t] = val;
    }
}

// ---------------------------------------------------------------------------
// qk partial: 64c x 128k tile, 256 threads, 2 CTAs/SM.
// grid (4 kt, 4 lp, 16 = b*2+ct)
// ---------------------------------------------------------------------------
#define QK_SMEM ((2*AW + 2*WW) * 4)   // 104448 B
__global__ __launch_bounds__(256, 2) void qk_v8(
    const float* __restrict__ q, const float* __restrict__ K,
    float* __restrict__ atp)
{
    extern __shared__ uint32_t smu[];
    uint32_t* Qh = smu;                // [64][NW]
    uint32_t* Ql = smu + AW;
    uint32_t* Kh = smu + 2 * AW;       // [128][NW]
    uint32_t* Kl = smu + 2 * AW + WW;
    const int tid = threadIdx.x;
    const int lane = tid & 31, wid = tid >> 5;
    const int gid = lane >> 2, tig = lane & 3;
    const int kt = blockIdx.x * 128, lp = blockIdx.y;
    const int b = blockIdx.z >> 1, ct = blockIdx.z & 1;
    const int c0 = ct * 64;
    const float* qp = q + (long)b * CL + (long)c0 * Lsp;
    const float* Kp = K + (long)b * C4L + (long)kt * Lsp;
    const int lbase = lp * 1024;

    const int m0b = (wid >> 2) * 32, n0b = (wid & 3) * 32;
    float acc[8][4];
#pragma unroll
    for (int i = 0; i < 8; i++)
#pragma unroll
        for (int j = 0; j < 4; j++) acc[i][j] = 0.f;

    for (int lc = 0; lc < 1024; lc += 128) {
        const int l0 = lbase + lc;
        __syncthreads();
#pragma unroll
        for (int j = 0; j < 8; j++) {       // Q: 64 rows x 32 f4
            int idx = tid + j * 256;
            int r = idx >> 5, c4 = idx & 31;
            float4 a = *(const float4*)&qp[(long)r * Lsp + l0 + c4 * 4];
            uint32_t h0, l0w, h1, l1w;
            packbf2(a.x, a.y, h0, l0w); packbf2(a.z, a.w, h1, l1w);
            *(uint2*)&Qh[r * NW + c4 * 2] = make_uint2(h0, h1);
            *(uint2*)&Ql[r * NW + c4 * 2] = make_uint2(l0w, l1w);
        }
#pragma unroll
        for (int j = 0; j < 16; j++) {      // K: 128 rows x 32 f4
            int idx = tid + j * 256;
            int r = idx >> 5, c4 = idx & 31;
            float4 kk = *(const float4*)&Kp[(long)r * Lsp + l0 + c4 * 4];
            uint32_t h0, l0w, h1, l1w;
            packbf2(kk.x, kk.y, h0, l0w); packbf2(kk.z, kk.w, h1, l1w);
            *(uint2*)&Kh[r * NW + c4 * 2] = make_uint2(h0, h1);
            *(uint2*)&Kl[r * NW + c4 * 2] = make_uint2(l0w, l1w);
        }
        __syncthreads();
#pragma unroll
        for (int k0 = 0; k0 < 128; k0 += 16) {
            const int kw = k0 / 2 + tig;
            uint32_t bh[4][2], bl[4][2];
#pragma unroll
            for (int nt = 0; nt < 4; nt++) {
                int n = n0b + nt * 8 + gid;
                bh[nt][0] = Kh[n * NW + kw];     bh[nt][1] = Kh[n * NW + kw + 4];
                bl[nt][0] = Kl[n * NW + kw];     bl[nt][1] = Kl[n * NW + kw + 4];
            }
#pragma unroll
            for (int mt = 0; mt < 2; mt++) {
                int r0 = m0b + mt * 16 + gid, r1 = r0 + 8;
                uint32_t ah[4], al[4];
                ah[0] = Qh[r0 * NW + kw];     ah[1] = Qh[r1 * NW + kw];
                ah[2] = Qh[r0 * NW + kw + 4]; ah[3] = Qh[r1 * NW + kw + 4];
                al[0] = Ql[r0 * NW + kw];     al[1] = Ql[r1 * NW + kw];
                al[2] = Ql[r0 * NW + kw + 4]; al[3] = Ql[r1 * NW + kw + 4];
#pragma unroll
                for (int nt = 0; nt < 4; nt++)
                    mma3bf(acc[mt * 4 + nt], ah, al,
                           bh[nt][0], bh[nt][1], bl[nt][0], bl[nt][1]);
            }
        }
    }
    float* ap = atp + (long)lp * (Bb * 65536) + (long)b * 65536 + (long)c0 * 512;
#pragma unroll
    for (int mt = 0; mt < 2; mt++)
#pragma unroll
        for (int nt = 0; nt < 4; nt++) {
            int m = m0b + mt * 16 + gid;
            int n = kt + n0b + nt * 8 + tig * 2;
            float* a = acc[mt * 4 + nt];
            *(float2*)&ap[(long)m * 512 + n] = make_float2(a[0], a[1]);
            *(float2*)&ap[(long)(m + 8) * 512 + n] = make_float2(a[2], a[3]);
        }
}

// ---------------------------------------------------------------------------
// masked softmax: sums 4 qk partials, scales by 1/64, writes probs
// ---------------------------------------------------------------------------
__global__ __launch_bounds__(128) void softmax_v6(
    const float* __restrict__ atp, float* __restrict__ at,
    const int* __restrict__ mask)
{
    __shared__ float sm[128];
    const int row = blockIdx.x;
    const int b = row >> 7;
    const int t = threadIdx.x;
    const float sc = 0.015625f;
    const long roff = (long)row * 512;
    const long pstr = (long)Bb * 65536;

    float v[4];
    float mx = -INFINITY;
#pragma unroll
    for (int j = 0; j < 4; j++) {
        bool on = mask[b * 4 + j] > 0;
        float sum = atp[roff + j * 128 + t] + atp[pstr + roff + j * 128 + t]
                  + atp[2 * pstr + roff + j * 128 + t] + atp[3 * pstr + roff + j * 128 + t];
        v[j] = on ? sum * sc : -INFINITY;
        mx = fmaxf(mx, v[j]);
    }
    sm[t] = mx; __syncthreads();
    for (int s = 64; s > 0; s >>= 1) {
        if (t < s) sm[t] = fmaxf(sm[t], sm[t + s]);
        __syncthreads();
    }
    mx = sm[0]; __syncthreads();

    float sum = 0.f;
#pragma unroll
    for (int j = 0; j < 4; j++) {
        v[j] = (v[j] == -INFINITY) ? 0.f : expf(v[j] - mx);
        sum += v[j];
    }
    sm[t] = sum; __syncthreads();
    for (int s = 64; s > 0; s >>= 1) {
        if (t < s) sm[t] += sm[t + s];
        __syncthreads();
    }
    float inv = 1.f / sm[0];
#pragma unroll
    for (int j = 0; j < 4; j++) at[roff + j * 128 + t] = v[j] * inv;
}

// ---------------------------------------------------------------------------
// av: x[b,c,lt+n] = sum_k attn[b,c,k] V[b,k,lt+n]  (3xTF32)
// ---------------------------------------------------------------------------
#define AV_SMEM ((128*68 + 64*136) * 4)
__global__ __launch_bounds__(256) void av_mma(
    const float* __restrict__ at, const float* __restrict__ V,
    float* __restrict__ xout)
{
    extern __shared__ float sm[];
    float* Aa = sm;                  // [128][68]
    float* Vs = sm + 128 * 68;       // [64][136]
    const int tid = threadIdx.x;
    const int lane = tid & 31, wid = tid >> 5;
    const int gid = lane >> 2, tig = lane & 3;
    const int lt = blockIdx.x * 128;
    const int b = blockIdx.y;
    const float* ap = at + (long)b * 65536;
    const float* Vp = V + (long)b * C4L;

    const int wm = wid >> 2, wn = wid & 3;
    const int m0b = wm * 64, n0b = wn * 32;
    float acc[16][4];
#pragma unroll
    for (int i = 0; i < 16; i++)
#pragma unroll
        for (int j = 0; j < 4; j++) acc[i][j] = 0.f;

    for (int kg = 0; kg < 512; kg += 64) {
        __syncthreads();
#pragma unroll 4
        for (int i = 0; i < 8; i++) {
            int idx = tid + i * 256;
            int r = idx >> 4, c4 = idx & 15;
            *(float4*)&Aa[r * 68 + c4 * 4] = *(const float4*)&ap[(long)r * 512 + kg + c4 * 4];
        }
#pragma unroll 4
        for (int i = 0; i < 8; i++) {
            int idx = tid + i * 256;
            int r = idx >> 5, c4 = idx & 31;
            *(float4*)&Vs[r * 136 + c4 * 4] =
                *(const float4*)&Vp[(long)(kg + r) * Lsp + lt + c4 * 4];
        }
        __syncthreads();
        for (int k0 = 0; k0 < 64; k0 += 8) {
            uint32_t bh[4][2], bl[4][2];
#pragma unroll
            for (int nt = 0; nt < 4; nt++) {
                int n = n0b + nt * 8 + gid;
                split32(Vs[(k0 + tig) * 136 + n],     bh[nt][0], bl[nt][0]);
                split32(Vs[(k0 + tig + 4) * 136 + n], bh[nt][1], bl[nt][1]);
            }
#pragma unroll
            for (int mt = 0; mt < 4; mt++) {
                int m = m0b + mt * 16 + gid;
                uint32_t ah[4], al[4];
                split32(Aa[m * 68 + k0 + tig],           ah[0], al[0]);
                split32(Aa[(m + 8) * 68 + k0 + tig],     ah[1], al[1]);
                split32(Aa[m * 68 + k0 + tig + 4],       ah[2], al[2]);
                split32(Aa[(m + 8) * 68 + k0 + tig + 4], ah[3], al[3]);
#pragma unroll
                for (int nt = 0; nt < 4; nt++)
                    mma3(acc[mt * 4 + nt], ah, al,
                         bh[nt][0], bh[nt][1], bl[nt][0], bl[nt][1]);
            }
        }
    }
    float* xp = xout + (long)b * CL + lt;
#pragma unroll
    for (int mt = 0; mt < 4; mt++)
#pragma unroll
        for (int nt = 0; nt < 4; nt++) {
            int m = m0b + mt * 16 + gid;
            int n = n0b + nt * 8 + tig * 2;
            float* a = acc[mt * 4 + nt];
            *(float2*)&xp[(long)m * Lsp + n] = make_float2(a[0], a[1]);
            *(float2*)&xp[(long)(m + 8) * Lsp + n] = make_float2(a[2], a[3]);
        }
}

// ---------------------------------------------------------------------------
// Depthwise 3x3x3 + bias, float4 loads
// ---------------------------------------------------------------------------
__global__ __launch_bounds__(256) void dw_v3(
    const float* __restrict__ inb, float* __restrict__ outb,
    long iz, long ib,
    const float* __restrict__ w27b, const float* __restrict__ biasb, int blk0)
{
    __shared__ float sp[16 * 324];
    const int tid = threadIdx.x;
    const int x = tid & 15, y = tid >> 4;
    const int c = blockIdx.x, b = blockIdx.y, z = blockIdx.z;
    const int blk = blk0 + z;

    const float* in = inb + (long)z * iz + (long)b * ib + (long)c * Lsp;
    float* out = outb + (long)z * iz + (long)b * ib + (long)c * Lsp;
    const float* wv = w27b + (long)blk * Cch * 27 + c * 27;
    const float bias = biasb[blk * Cch + c];

    for (int idx = tid; idx < 16 * 324; idx += 256) sp[idx] = 0.f;
    __syncthreads();
    const float4* in4 = (const float4*)in;
#pragma unroll
    for (int j = 0; j < 4; j++) {
        int i4 = tid + j * 256;             // 1024 float4 = 16^3
        float4 vv = in4[i4];
        int zz = i4 >> 6, rem = i4 & 63;
        float* dst = &sp[zz * 324 + ((rem >> 2) + 1) * 18 + (rem & 3) * 4 + 1];
        dst[0] = vv.x; dst[1] = vv.y; dst[2] = vv.z; dst[3] = vv.w;
    }
    float w[27];
#pragma unroll
    for (int k = 0; k < 27; k++) w[k] = wv[k];
    __syncthreads();

    float p0[9], p1[9], p2[9];
#pragma unroll
    for (int k = 0; k < 9; k++) p0[k] = 0.f;
#pragma unroll
    for (int dy = 0; dy < 3; dy++)
#pragma unroll
        for (int dx = 0; dx < 3; dx++)
            p1[dy * 3 + dx] = sp[(y + dy) * 18 + (x + dx)];

#pragma unroll
    for (int zz = 0; zz < 16; zz++) {
        if (zz < 15) {
#pragma unroll
            for (int dy = 0; dy < 3; dy++)
#pragma unroll
                for (int dx = 0; dx < 3; dx++)
                    p2[dy * 3 + dx] = sp[(zz + 1) * 324 + (y + dy) * 18 + (x + dx)];
        } else {
#pragma unroll
            for (int k = 0; k < 9; k++) p2[k] = 0.f;
        }
        float a = bias;
#pragma unroll
        for (int k = 0; k < 9; k++) a += p0[k] * w[k];
#pragma unroll
        for (int k = 0; k < 9; k++) a += p1[k] * w[9 + k];
#pragma unroll
        for (int k = 0; k < 9; k++) a += p2[k] * w[18 + k];
        out[zz * 256 + tid] = a;
#pragma unroll
        for (int k = 0; k < 9; k++) { p0[k] = p1[k]; p1[k] = p2[k]; }
    }
}

// ---------------------------------------------------------------------------
extern "C" void kernel_launch(void* const* d_in, const int* in_sizes, int n_in,
                              void* d_out, int out_size)
{
    const float* query = (const float*)d_in[0];
    const float* m0 = (const float*)d_in[1];
    const float* m1 = (const float*)d_in[2];
    const float* m2 = (const float*)d_in[3];
    const float* m3 = (const float*)d_in[4];
    const int*   mask  = (const int*)d_in[5];
    const float* pw1_w = (const float*)d_in[6];
    const float* pw1_b = (const float*)d_in[7];
    const float* ln1_g = (const float*)d_in[8];
    const float* ln1_b = (const float*)d_in[9];
    const float* dw_w  = (const float*)d_in[10];
    const float* dw_b  = (const float*)d_in[11];
    const float* ln2_g = (const float*)d_in[12];
    const float* ln2_b = (const float*)d_in[13];
    const float* pw2_w = (const float*)d_in[14];
    const float* pw2_b = (const float*)d_in[15];
    const float* ln3_g = (const float*)d_in[16];
    const float* ln3_b = (const float*)d_in[17];
    float* out = (float*)d_out;

    float *y1, *y2, *qb, *kv, *xb, *at, *atp;
    cudaGetSymbolAddress((void**)&y1, g_y1);
    cudaGetSymbolAddress((void**)&y2, g_y2);
    cudaGetSymbolAddress((void**)&qb, g_q);
    cudaGetSymbolAddress((void**)&kv, g_KV);
    cudaGetSymbolAddress((void**)&xb, g_x);
    cudaGetSymbolAddress((void**)&at, g_at);
    cudaGetSymbolAddress((void**)&atp, g_atp);
    float* Kb = kv;
    float* Vb = kv + (long)Bb * C4L;

    cudaFuncSetAttribute(pw_v8, cudaFuncAttributeMaxDynamicSharedMemorySize, PW_SMEM);
    cudaFuncSetAttribute(qk_v8, cudaFuncAttributeMaxDynamicSharedMemorySize, QK_SMEM);
    cudaFuncSetAttribute(av_mma, cudaFuncAttributeMaxDynamicSharedMemorySize, AV_SMEM);

    // ---- blocks 0..8 (query + K/V maps) in one chain of 3 launches ----
    pw_v8<<<dim3(64, Bb, 9), 256, PW_SMEM>>>(
        query, m0, m1, m2, m3, /*imode=*/1,
        pw1_w, pw1_b, ln1_g, ln1_b, ln1_g, ln1_b, /*blk0=*/0,
        nullptr, y1, nullptr, /*omode=*/1, /*flags=*/2);
    dw_v3<<<dim3(Cch, Bb, 9), 256>>>(y1, y2, BCL, CL, dw_w, dw_b, 0);
    pw_v8<<<dim3(64, Bb, 9), 256, PW_SMEM>>>(
        y2, nullptr, nullptr, nullptr, nullptr, /*imode=*/2,
        pw2_w, pw2_b, ln2_g, ln2_b, ln3_g, ln3_b, /*blk0=*/0,
        nullptr, qb, kv, /*omode=*/2, /*flags=*/1);

    // ---- attention ----
    qk_v8<<<dim3(4, 4, 16), 256, QK_SMEM>>>(qb, Kb, atp);
    softmax_v6<<<Bb * 128, 128>>>(atp, at, mask);
    av_mma<<<dim3(32, Bb), 256, AV_SMEM>>>(at, Vb, xb);

    // ---- out_project (blk 9) + residual ----
    pw_v8<<<dim3(64, Bb, 1), 256, PW_SMEM>>>(
        xb, nullptr, nullptr, nullptr, nullptr, /*imode=*/0,
        pw1_w, pw1_b, ln1_g, ln1_b, ln1_g, ln1_b, /*blk0=*/9,
        nullptr, y1, nullptr, /*omode=*/0, /*flags=*/2);
    dw_v3<<<dim3(Cch, Bb, 1), 256>>>(y1, y2, BCL, CL, dw_w, dw_b, 9);
    pw_v8<<<dim3(64, Bb, 1), 256, PW_SMEM>>>(
        y2, nullptr, nullptr, nullptr, nullptr, /*imode=*/0,
        pw2_w, pw2_b, ln2_g, ln2_b, ln3_g, ln3_b, /*blk0=*/9,
        query, out, nullptr, /*omode=*/0, /*flags=*/1 | 4);
}

// round 9
// speedup vs baseline: 2.9756x; 1.0004x over previous
#include <cuda_runtime.h>
#include <math.h>
#include <stdint.h>

#define Bb   8
#define Cch  128
#define Lsp  4096
#define CL   (Cch*Lsp)        // 524288
#define C4L  (4*CL)
#define BCL  (Bb*CL)

// ---------------- scratch (static device memory) ----------------------------
__device__ float g_y1[9*BCL];
__device__ float g_y2[9*BCL];
__device__ float g_q [BCL];
__device__ float g_KV[2*Bb*C4L];
__device__ float g_x [BCL];
__device__ float g_at [Bb*128*512];      // final softmax probs
__device__ float g_atp[4*Bb*128*512];    // qk partials (4 L-parts)

__device__ __forceinline__ float gelu_exact(float x) {
    return 0.5f * x * (1.0f + erff(x * 0.70710678118654752f));
}

// ======================= bf16 hi/lo split-pack ==============================
__device__ __forceinline__ void packbf2(float x0, float x1, uint32_t& h, uint32_t& l) {
    asm("cvt.rn.bf16x2.f32 %0, %1, %2;" : "=r"(h) : "f"(x1), "f"(x0));
    float h0 = __uint_as_float(h << 16);
    float h1 = __uint_as_float(h & 0xffff0000u);
    asm("cvt.rn.bf16x2.f32 %0, %1, %2;" : "=r"(l) : "f"(x1 - h1), "f"(x0 - h0));
}

__device__ __forceinline__ void mmabf(float* d,
    uint32_t a0, uint32_t a1, uint32_t a2, uint32_t a3, uint32_t b0, uint32_t b1)
{
    asm volatile(
        "mma.sync.aligned.m16n8k16.row.col.f32.bf16.bf16.f32 "
        "{%0,%1,%2,%3}, {%4,%5,%6,%7}, {%8,%9}, {%0,%1,%2,%3};"
        : "+f"(d[0]), "+f"(d[1]), "+f"(d[2]), "+f"(d[3])
        : "r"(a0), "r"(a1), "r"(a2), "r"(a3), "r"(b0), "r"(b1));
}
__device__ __forceinline__ void mma3bf(float* d,
    const uint32_t* ah, const uint32_t* al,
    uint32_t bh0, uint32_t bh1, uint32_t bl0, uint32_t bl1)
{
    mmabf(d, ah[0], ah[1], ah[2], ah[3], bl0, bl1);
    mmabf(d, al[0], al[1], al[2], al[3], bh0, bh1);
    mmabf(d, ah[0], ah[1], ah[2], ah[3], bh0, bh1);
}

// ---- tf32 helpers (av kernel) ----------------------------------------------
__device__ __forceinline__ void mma8(float* d,
    uint32_t a0, uint32_t a1, uint32_t a2, uint32_t a3, uint32_t b0, uint32_t b1)
{
    asm volatile(
        "mma.sync.aligned.m16n8k8.row.col.f32.tf32.tf32.f32 "
        "{%0,%1,%2,%3}, {%4,%5,%6,%7}, {%8,%9}, {%0,%1,%2,%3};"
        : "+f"(d[0]), "+f"(d[1]), "+f"(d[2]), "+f"(d[3])
        : "r"(a0), "r"(a1), "r"(a2), "r"(a3), "r"(b0), "r"(b1));
}
__device__ __forceinline__ uint32_t tf32r(float x) {
    uint32_t r; asm("cvt.rna.tf32.f32 %0, %1;" : "=r"(r) : "f"(x)); return r;
}
__device__ __forceinline__ void split32(float x, uint32_t& h, uint32_t& l) {
    h = tf32r(x); l = tf32r(x - __uint_as_float(h));
}
__device__ __forceinline__ void mma3(float* d,
    const uint32_t* ah, const uint32_t* al,
    uint32_t bh0, uint32_t bh1, uint32_t bl0, uint32_t bl1)
{
    mma8(d, ah[0], ah[1], ah[2], ah[3], bl0, bl1);
    mma8(d, al[0], al[1], al[2], al[3], bh0, bh1);
    mma8(d, ah[0], ah[1], ah[2], ah[3], bh0, bh1);
}

// ---------------------------------------------------------------------------
// Fused pointwise block: 64-token x 128-out tile, 256 threads, 2 CTAs/SM.
// imode: 0 inq+b*CL | 1 (z==0?inq:mods[(z-1)&3])+b*CL | 2 inq+z*BCL+b*CL
// omode: 0 out0+b*CL | 1 out0+z*BCL+b*CL | 2 z==0->out0, else KV layout
// flags: bit0 in LN+GELU, bit1 out GELU, bit2 residual
// ---------------------------------------------------------------------------
#define NW 68
#define AW (64*NW)      // 4352 words per A array
#define WW (128*NW)     // 8704 words per W array
#define CS_STR 132
#define PW_SMEM ((2*AW + 2*WW + 512 + 384) * 4)   // 108032 B

__global__ __launch_bounds__(256, 2) void pw_v8(
    const float* __restrict__ inq,
    const float* __restrict__ mm0, const float* __restrict__ mm1,
    const float* __restrict__ mm2, const float* __restrict__ mm3,
    int imode,
    const float* __restrict__ Wb, const float* __restrict__ biasb,
    const float* __restrict__ g1b, const float* __restrict__ b1b,
    const float* __restrict__ g2b, const float* __restrict__ b2b,
    int blk0,
    const float* __restrict__ res,
    float* __restrict__ out0, float* __restrict__ out1, int omode,
    int flags)
{
    extern __shared__ uint32_t smu[];
    uint32_t* Ah = smu;                // [64][NW]
    uint32_t* Al = smu + AW;
    uint32_t* Wh = smu + 2 * AW;       // [128][NW]
    uint32_t* Wl = smu + 2 * AW + WW;
    float* red = (float*)(smu + 2 * AW + 2 * WW);   // [2][4][64]
    float* ps  = red + 512;                          // bias | go | bo
    float* Cs  = (float*)smu;                        // epilogue alias (A region)

    const int tid = threadIdx.x;
    const int lane = tid & 31, wid = tid >> 5;
    const int gid = lane >> 2, tig = lane & 3;
    const int t = tid & 63, p = tid >> 6;       // token, channel-quarter
    const int cb = p * 32;
    const int b = blockIdx.y, z = blockIdx.z;
    const int l0 = blockIdx.x * 64;
    const int blk = blk0 + z;

    const float* src;
    if (imode == 0) src = inq;
    else if (imode == 1) {
        if (z == 0) src = inq;
        else { int zs = (z - 1) & 3; src = zs == 0 ? mm0 : zs == 1 ? mm1 : zs == 2 ? mm2 : mm3; }
    } else src = inq + (long)z * BCL;
    const float* inp = src + (long)b * CL + l0;

    float* outp;
    if (omode == 0) outp = out0 + (long)b * CL + l0;
    else if (omode == 1) outp = out0 + (long)z * BCL + (long)b * CL + l0;
    else {
        if (z == 0) outp = out0 + (long)b * CL + l0;
        else {
            int z1 = z - 1;
            outp = out1 + (long)(z1 >> 2) * ((long)Bb * C4L)
                 + (long)(z1 & 3) * CL + (long)b * C4L + l0;
        }
    }

    const float* W    = Wb + (long)blk * 128 * 128;
    const float* bias = biasb + blk * 128;
    const float* gi = g1b + blk * 128, *bi = b1b + blk * 128;
    const float* go = g2b + blk * 128, *bo = b2b + blk * 128;

    // ---- A loads: 4 threads per token, 32 channels each ----
    float v[32];
    float s = 0.f, q = 0.f;
#pragma unroll
    for (int i = 0; i < 32; i++) {
        v[i] = inp[(long)(cb + i) * Lsp + t];
        s += v[i]; q += v[i] * v[i];
    }
    // ---- W staging: float4 -> split bf16x2 pairs ----
#pragma unroll
    for (int j = 0; j < 16; j++) {
        int idx = tid + j * 256;
        int o = idx >> 5, c4 = idx & 31;
        float4 w = *(const float4*)&W[o * 128 + c4 * 4];
        uint32_t h0, l0w, h1, l1w;
        packbf2(w.x, w.y, h0, l0w);
        packbf2(w.z, w.w, h1, l1w);
        *(uint2*)&Wh[o * NW + c4 * 2] = make_uint2(h0, h1);
        *(uint2*)&Wl[o * NW + c4 * 2] = make_uint2(l0w, l1w);
    }
    if (tid < 128) { ps[tid] = bias[tid]; ps[128 + tid] = go[tid]; ps[256 + tid] = bo[tid]; }

    if (flags & 1) {
        red[p * 64 + t] = s; red[256 + p * 64 + t] = q;
        __syncthreads();
        float S = red[t] + red[64 + t] + red[128 + t] + red[192 + t];
        float Q = red[256 + t] + red[320 + t] + red[384 + t] + red[448 + t];
        float mean = S * (1.f / 128.f);
        float rstd = rsqrtf(Q * (1.f / 128.f) - mean * mean + 1e-6f);
#pragma unroll
        for (int i = 0; i < 16; i++) {
            float x0 = gelu_exact((v[2*i]   - mean) * rstd * gi[cb + 2*i]   + bi[cb + 2*i]);
            float x1 = gelu_exact((v[2*i+1] - mean) * rstd * gi[cb + 2*i+1] + bi[cb + 2*i+1]);
            uint32_t h, l;
            packbf2(x0, x1, h, l);
            Ah[t * NW + cb / 2 + i] = h;
            Al[t * NW + cb / 2 + i] = l;
        }
    } else {
#pragma unroll
        for (int i = 0; i < 16; i++) {
            uint32_t h, l;
            packbf2(v[2*i], v[2*i+1], h, l);
            Ah[t * NW + cb / 2 + i] = h;
            Al[t * NW + cb / 2 + i] = l;
        }
    }
    __syncthreads();

    // ---- mainloop: 8 warps (2m x 4n), warp tile m32 x n32 ----
    const int m0b = (wid >> 2) * 32, n0b = (wid & 3) * 32;
    float acc[8][4];
#pragma unroll
    for (int i = 0; i < 8; i++)
#pragma unroll
        for (int j = 0; j < 4; j++) acc[i][j] = 0.f;

#pragma unroll
    for (int k0 = 0; k0 < 128; k0 += 16) {
        const int kw = k0 / 2 + tig;
        uint32_t bh[4][2], bl[4][2];
#pragma unroll
        for (int nt = 0; nt < 4; nt++) {
            int n = n0b + nt * 8 + gid;
            bh[nt][0] = Wh[n * NW + kw];     bh[nt][1] = Wh[n * NW + kw + 4];
            bl[nt][0] = Wl[n * NW + kw];     bl[nt][1] = Wl[n * NW + kw + 4];
        }
#pragma unroll
        for (int mt = 0; mt < 2; mt++) {
            int r0 = m0b + mt * 16 + gid, r1 = r0 + 8;
            uint32_t ah[4], al[4];
            ah[0] = Ah[r0 * NW + kw];     ah[1] = Ah[r1 * NW + kw];
            ah[2] = Ah[r0 * NW + kw + 4]; ah[3] = Ah[r1 * NW + kw + 4];
            al[0] = Al[r0 * NW + kw];     al[1] = Al[r1 * NW + kw];
            al[2] = Al[r0 * NW + kw + 4]; al[3] = Al[r1 * NW + kw + 4];
#pragma unroll
            for (int nt = 0; nt < 4; nt++)
                mma3bf(acc[mt * 4 + nt], ah, al,
                       bh[nt][0], bh[nt][1], bl[nt][0], bl[nt][1]);
        }
    }
    __syncthreads();

    // ---- C -> smem (alias A region: 64 x CS_STR <= 2*AW) ----
#pragma unroll
    for (int mt = 0; mt < 2; mt++)
#pragma unroll
        for (int nt = 0; nt < 4; nt++) {
            int m = m0b + mt * 16 + gid, n = n0b + nt * 8 + tig * 2;
            float* a = acc[mt * 4 + nt];
            *(float2*)&Cs[m * CS_STR + n] = make_float2(a[0], a[1]);
            *(float2*)&Cs[(m + 8) * CS_STR + n] = make_float2(a[2], a[3]);
        }
    __syncthreads();

    // ---- epilogue: +bias -> LN -> [GELU] -> [res] ----
    float w2[32];
    float s2 = 0.f, q2 = 0.f;
#pragma unroll
    for (int i = 0; i < 32; i++) {
        w2[i] = Cs[t * CS_STR + cb + i] + ps[cb + i];
        s2 += w2[i]; q2 += w2[i] * w2[i];
    }
    red[p * 64 + t] = s2; red[256 + p * 64 + t] = q2;
    __syncthreads();
    float S2 = red[t] + red[64 + t] + red[128 + t] + red[192 + t];
    float Q2 = red[256 + t] + red[320 + t] + red[384 + t] + red[448 + t];
    float mean2 = S2 * (1.f / 128.f);
    float rstd2 = rsqrtf(Q2 * (1.f / 128.f) - mean2 * mean2 + 1e-6f);
    const float* resp = (flags & 4) ? (res + (long)b * CL + l0) : nullptr;
#pragma unroll
    for (int i = 0; i < 32; i++) {
        int c = cb + i;
        float val = (w2[i] - mean2) * rstd2 * ps[128 + c] + ps[256 + c];
        if (flags & 2) val = gelu_exact(val);
        if (flags & 4) val += resp[(long)c * Lsp + t];
        outp[(long)c * Lsp + t] = val;
    }
}

// ---------------------------------------------------------------------------
// qk partial: 64c x 128k tile, 256 threads, 2 CTAs/SM.
// grid (4 kt, 4 lp, 16 = b*2+ct)
// ---------------------------------------------------------------------------
#define QK_SMEM ((2*AW + 2*WW) * 4)   // 104448 B
__global__ __launch_bounds__(256, 2) void qk_v8(
    const float* __restrict__ q, const float* __restrict__ K,
    float* __restrict__ atp)
{
    extern __shared__ uint32_t smu[];
    uint32_t* Qh = smu;                // [64][NW]
    uint32_t* Ql = smu + AW;
    uint32_t* Kh = smu + 2 * AW;       // [128][NW]
    uint32_t* Kl = smu + 2 * AW + WW;
    const int tid = threadIdx.x;
    const int lane = tid & 31, wid = tid >> 5;
    const int gid = lane >> 2, tig = lane & 3;
    const int kt = blockIdx.x * 128, lp = blockIdx.y;
    const int b = blockIdx.z >> 1, ct = blockIdx.z & 1;
    const int c0 = ct * 64;
    const float* qp = q + (long)b * CL + (long)c0 * Lsp;
    const float* Kp = K + (long)b * C4L + (long)kt * Lsp;
    const int lbase = lp * 1024;

    const int m0b = (wid >> 2) * 32, n0b = (wid & 3) * 32;
    float acc[8][4];
#pragma unroll
    for (int i = 0; i < 8; i++)
#pragma unroll
        for (int j = 0; j < 4; j++) acc[i][j] = 0.f;

    for (int lc = 0; lc < 1024; lc += 128) {
        const int l0 = lbase + lc;
        __syncthreads();
#pragma unroll
        for (int j = 0; j < 8; j++) {       // Q: 64 rows x 32 f4
            int idx = tid + j * 256;
            int r = idx >> 5, c4 = idx & 31;
            float4 a = *(const float4*)&qp[(long)r * Lsp + l0 + c4 * 4];
            uint32_t h0, l0w, h1, l1w;
            packbf2(a.x, a.y, h0, l0w); packbf2(a.z, a.w, h1, l1w);
            *(uint2*)&Qh[r * NW + c4 * 2] = make_uint2(h0, h1);
            *(uint2*)&Ql[r * NW + c4 * 2] = make_uint2(l0w, l1w);
        }
#pragma unroll
        for (int j = 0; j < 16; j++) {      // K: 128 rows x 32 f4
            int idx = tid + j * 256;
            int r = idx >> 5, c4 = idx & 31;
            float4 kk = *(const float4*)&Kp[(long)r * Lsp + l0 + c4 * 4];
            uint32_t h0, l0w, h1, l1w;
            packbf2(kk.x, kk.y, h0, l0w); packbf2(kk.z, kk.w, h1, l1w);
            *(uint2*)&Kh[r * NW + c4 * 2] = make_uint2(h0, h1);
            *(uint2*)&Kl[r * NW + c4 * 2] = make_uint2(l0w, l1w);
        }
        __syncthreads();
#pragma unroll
        for (int k0 = 0; k0 < 128; k0 += 16) {
            const int kw = k0 / 2 + tig;
            uint32_t bh[4][2], bl[4][2];
#pragma unroll
            for (int nt = 0; nt < 4; nt++) {
                int n = n0b + nt * 8 + gid;
                bh[nt][0] = Kh[n * NW + kw];     bh[nt][1] = Kh[n * NW + kw + 4];
                bl[nt][0] = Kl[n * NW + kw];     bl[nt][1] = Kl[n * NW + kw + 4];
            }
#pragma unroll
            for (int mt = 0; mt < 2; mt++) {
                int r0 = m0b + mt * 16 + gid, r1 = r0 + 8;
                uint32_t ah[4], al[4];
                ah[0] = Qh[r0 * NW + kw];     ah[1] = Qh[r1 * NW + kw];
                ah[2] = Qh[r0 * NW + kw + 4]; ah[3] = Qh[r1 * NW + kw + 4];
                al[0] = Ql[r0 * NW + kw];     al[1] = Ql[r1 * NW + kw];
                al[2] = Ql[r0 * NW + kw + 4]; al[3] = Ql[r1 * NW + kw + 4];
#pragma unroll
                for (int nt = 0; nt < 4; nt++)
                    mma3bf(acc[mt * 4 + nt], ah, al,
                           bh[nt][0], bh[nt][1], bl[nt][0], bl[nt][1]);
            }
        }
    }
    float* ap = atp + (long)lp * (Bb * 65536) + (long)b * 65536 + (long)c0 * 512;
#pragma unroll
    for (int mt = 0; mt < 2; mt++)
#pragma unroll
        for (int nt = 0; nt < 4; nt++) {
            int m = m0b + mt * 16 + gid;
            int n = kt + n0b + nt * 8 + tig * 2;
            float* a = acc[mt * 4 + nt];
            *(float2*)&ap[(long)m * 512 + n] = make_float2(a[0], a[1]);
            *(float2*)&ap[(long)(m + 8) * 512 + n] = make_float2(a[2], a[3]);
        }
}

// ---------------------------------------------------------------------------
// masked softmax: sums 4 qk partials, scales by 1/64, writes probs
// ---------------------------------------------------------------------------
__global__ __launch_bounds__(128) void softmax_v6(
    const float* __restrict__ atp, float* __restrict__ at,
    const int* __restrict__ mask)
{
    __shared__ float sm[128];
    const int row = blockIdx.x;
    const int b = row >> 7;
    const int t = threadIdx.x;
    const float sc = 0.015625f;
    const long roff = (long)row * 512;
    const long pstr = (long)Bb * 65536;

    float v[4];
    float mx = -INFINITY;
#pragma unroll
    for (int j = 0; j < 4; j++) {
        bool on = mask[b * 4 + j] > 0;
        float sum = atp[roff + j * 128 + t] + atp[pstr + roff + j * 128 + t]
                  + atp[2 * pstr + roff + j * 128 + t] + atp[3 * pstr + roff + j * 128 + t];
        v[j] = on ? sum * sc : -INFINITY;
        mx = fmaxf(mx, v[j]);
    }
    sm[t] = mx; __syncthreads();
    for (int s = 64; s > 0; s >>= 1) {
        if (t < s) sm[t] = fmaxf(sm[t], sm[t + s]);
        __syncthreads();
    }
    mx = sm[0]; __syncthreads();

    float sum = 0.f;
#pragma unroll
    for (int j = 0; j < 4; j++) {
        v[j] = (v[j] == -INFINITY) ? 0.f : expf(v[j] - mx);
        sum += v[j];
    }
    sm[t] = sum; __syncthreads();
    for (int s = 64; s > 0; s >>= 1) {
        if (t < s) sm[t] += sm[t + s];
        __syncthreads();
    }
    float inv = 1.f / sm[0];
#pragma unroll
    for (int j = 0; j < 4; j++) at[roff + j * 128 + t] = v[j] * inv;
}

// ---------------------------------------------------------------------------
// av: x[b,c,lt+n] = sum_k attn[b,c,k] V[b,k,lt+n]  (3xTF32)
// ---------------------------------------------------------------------------
#define AV_SMEM ((128*68 + 64*136) * 4)
__global__ __launch_bounds__(256) void av_mma(
    const float* __restrict__ at, const float* __restrict__ V,
    float* __restrict__ xout)
{
    extern __shared__ float sm[];
    float* Aa = sm;                  // [128][68]
    float* Vs = sm + 128 * 68;       // [64][136]
    const int tid = threadIdx.x;
    const int lane = tid & 31, wid = tid >> 5;
    const int gid = lane >> 2, tig = lane & 3;
    const int lt = blockIdx.x * 128;
    const int b = blockIdx.y;
    const float* ap = at + (long)b * 65536;
    const float* Vp = V + (long)b * C4L;

    const int wm = wid >> 2, wn = wid & 3;
    const int m0b = wm * 64, n0b = wn * 32;
    float acc[16][4];
#pragma unroll
    for (int i = 0; i < 16; i++)
#pragma unroll
        for (int j = 0; j < 4; j++) acc[i][j] = 0.f;

    for (int kg = 0; kg < 512; kg += 64) {
        __syncthreads();
#pragma unroll 4
        for (int i = 0; i < 8; i++) {
            int idx = tid + i * 256;
            int r = idx >> 4, c4 = idx & 15;
            *(float4*)&Aa[r * 68 + c4 * 4] = *(const float4*)&ap[(long)r * 512 + kg + c4 * 4];
        }
#pragma unroll 4
        for (int i = 0; i < 8; i++) {
            int idx = tid + i * 256;
            int r = idx >> 5, c4 = idx & 31;
            *(float4*)&Vs[r * 136 + c4 * 4] =
                *(const float4*)&Vp[(long)(kg + r) * Lsp + lt + c4 * 4];
        }
        __syncthreads();
        for (int k0 = 0; k0 < 64; k0 += 8) {
            uint32_t bh[4][2], bl[4][2];
#pragma unroll
            for (int nt = 0; nt < 4; nt++) {
                int n = n0b + nt * 8 + gid;
                split32(Vs[(k0 + tig) * 136 + n],     bh[nt][0], bl[nt][0]);
                split32(Vs[(k0 + tig + 4) * 136 + n], bh[nt][1], bl[nt][1]);
            }
#pragma unroll
            for (int mt = 0; mt < 4; mt++) {
                int m = m0b + mt * 16 + gid;
                uint32_t ah[4], al[4];
                split32(Aa[m * 68 + k0 + tig],           ah[0], al[0]);
                split32(Aa[(m + 8) * 68 + k0 + tig],     ah[1], al[1]);
                split32(Aa[m * 68 + k0 + tig + 4],       ah[2], al[2]);
                split32(Aa[(m + 8) * 68 + k0 + tig + 4], ah[3], al[3]);
#pragma unroll
                for (int nt = 0; nt < 4; nt++)
                    mma3(acc[mt * 4 + nt], ah, al,
                         bh[nt][0], bh[nt][1], bl[nt][0], bl[nt][1]);
            }
        }
    }
    float* xp = xout + (long)b * CL + lt;
#pragma unroll
    for (int mt = 0; mt < 4; mt++)
#pragma unroll
        for (int nt = 0; nt < 4; nt++) {
            int m = m0b + mt * 16 + gid;
            int n = n0b + nt * 8 + tig * 2;
            float* a = acc[mt * 4 + nt];
            *(float2*)&xp[(long)m * Lsp + n] = make_float2(a[0], a[1]);
            *(float2*)&xp[(long)(m + 8) * Lsp + n] = make_float2(a[2], a[3]);
        }
}

// ---------------------------------------------------------------------------
// Depthwise 3x3x3 + bias, float4 loads
// ---------------------------------------------------------------------------
__global__ __launch_bounds__(256) void dw_v3(
    const float* __restrict__ inb, float* __restrict__ outb,
    long iz, long ib,
    const float* __restrict__ w27b, const float* __restrict__ biasb, int blk0)
{
    __shared__ float sp[16 * 324];
    const int tid = threadIdx.x;
    const int x = tid & 15, y = tid >> 4;
    const int c = blockIdx.x, b = blockIdx.y, z = blockIdx.z;
    const int blk = blk0 + z;

    const float* in = inb + (long)z * iz + (long)b * ib + (long)c * Lsp;
    float* out = outb + (long)z * iz + (long)b * ib + (long)c * Lsp;
    const float* wv = w27b + (long)blk * Cch * 27 + c * 27;
    const float bias = biasb[blk * Cch + c];

    for (int idx = tid; idx < 16 * 324; idx += 256) sp[idx] = 0.f;
    __syncthreads();
    const float4* in4 = (const float4*)in;
#pragma unroll
    for (int j = 0; j < 4; j++) {
        int i4 = tid + j * 256;             // 1024 float4 = 16^3
        float4 vv = in4[i4];
        int zz = i4 >> 6, rem = i4 & 63;
        float* dst = &sp[zz * 324 + ((rem >> 2) + 1) * 18 + (rem & 3) * 4 + 1];
        dst[0] = vv.x; dst[1] = vv.y; dst[2] = vv.z; dst[3] = vv.w;
    }
    float w[27];
#pragma unroll
    for (int k = 0; k < 27; k++) w[k] = wv[k];
    __syncthreads();

    float p0[9], p1[9], p2[9];
#pragma unroll
    for (int k = 0; k < 9; k++) p0[k] = 0.f;
#pragma unroll
    for (int dy = 0; dy < 3; dy++)
#pragma unroll
        for (int dx = 0; dx < 3; dx++)
            p1[dy * 3 + dx] = sp[(y + dy) * 18 + (x + dx)];

#pragma unroll
    for (int zz = 0; zz < 16; zz++) {
        if (zz < 15) {
#pragma unroll
            for (int dy = 0; dy < 3; dy++)
#pragma unroll
                for (int dx = 0; dx < 3; dx++)
                    p2[dy * 3 + dx] = sp[(zz + 1) * 324 + (y + dy) * 18 + (x + dx)];
        } else {
#pragma unroll
            for (int k = 0; k < 9; k++) p2[k] = 0.f;
        }
        float a = bias;
#pragma unroll
        for (int k = 0; k < 9; k++) a += p0[k] * w[k];
#pragma unroll
        for (int k = 0; k < 9; k++) a += p1[k] * w[9 + k];
#pragma unroll
        for (int k = 0; k < 9; k++) a += p2[k] * w[18 + k];
        out[zz * 256 + tid] = a;
#pragma unroll
        for (int k = 0; k < 9; k++) { p0[k] = p1[k]; p1[k] = p2[k]; }
    }
}

// ---------------------------------------------------------------------------
extern "C" void kernel_launch(void* const* d_in, const int* in_sizes, int n_in,
                              void* d_out, int out_size)
{
    const float* query = (const float*)d_in[0];
    const float* m0 = (const float*)d_in[1];
    const float* m1 = (const float*)d_in[2];
    const float* m2 = (const float*)d_in[3];
    const float* m3 = (const float*)d_in[4];
    const int*   mask  = (const int*)d_in[5];
    const float* pw1_w = (const float*)d_in[6];
    const float* pw1_b = (const float*)d_in[7];
    const float* ln1_g = (const float*)d_in[8];
    const float* ln1_b = (const float*)d_in[9];
    const float* dw_w  = (const float*)d_in[10];
    const float* dw_b  = (const float*)d_in[11];
    const float* ln2_g = (const float*)d_in[12];
    const float* ln2_b = (const float*)d_in[13];
    const float* pw2_w = (const float*)d_in[14];
    const float* pw2_b = (const float*)d_in[15];
    const float* ln3_g = (const float*)d_in[16];
    const float* ln3_b = (const float*)d_in[17];
    float* out = (float*)d_out;

    float *y1, *y2, *qb, *kv, *xb, *at, *atp;
    cudaGetSymbolAddress((void**)&y1, g_y1);
    cudaGetSymbolAddress((void**)&y2, g_y2);
    cudaGetSymbolAddress((void**)&qb, g_q);
    cudaGetSymbolAddress((void**)&kv, g_KV);
    cudaGetSymbolAddress((void**)&xb, g_x);
    cudaGetSymbolAddress((void**)&at, g_at);
    cudaGetSymbolAddress((void**)&atp, g_atp);
    float* Kb = kv;
    float* Vb = kv + (long)Bb * C4L;

    cudaFuncSetAttribute(pw_v8, cudaFuncAttributeMaxDynamicSharedMemorySize, PW_SMEM);
    cudaFuncSetAttribute(qk_v8, cudaFuncAttributeMaxDynamicSharedMemorySize, QK_SMEM);
    cudaFuncSetAttribute(av_mma, cudaFuncAttributeMaxDynamicSharedMemorySize, AV_SMEM);

    // ---- blocks 0..8 (query + K/V maps) in one chain of 3 launches ----
    pw_v8<<<dim3(64, Bb, 9), 256, PW_SMEM>>>(
        query, m0, m1, m2, m3, /*imode=*/1,
        pw1_w, pw1_b, ln1_g, ln1_b, ln1_g, ln1_b, /*blk0=*/0,
        nullptr, y1, nullptr, /*omode=*/1, /*flags=*/2);
    dw_v3<<<dim3(Cch, Bb, 9), 256>>>(y1, y2, BCL, CL, dw_w, dw_b, 0);
    pw_v8<<<dim3(64, Bb, 9), 256, PW_SMEM>>>(
        y2, nullptr, nullptr, nullptr, nullptr, /*imode=*/2,
        pw2_w, pw2_b, ln2_g, ln2_b, ln3_g, ln3_b, /*blk0=*/0,
        nullptr, qb, kv, /*omode=*/2, /*flags=*/1);

    // ---- attention ----
    qk_v8<<<dim3(4, 4, 16), 256, QK_SMEM>>>(qb, Kb, atp);
    softmax_v6<<<Bb * 128, 128>>>(atp, at, mask);
    av_mma<<<dim3(32, Bb), 256, AV_SMEM>>>(at, Vb, xb);

    // ---- out_project (blk 9) + residual ----
    pw_v8<<<dim3(64, Bb, 1), 256, PW_SMEM>>>(
        xb, nullptr, nullptr, nullptr, nullptr, /*imode=*/0,
        pw1_w, pw1_b, ln1_g, ln1_b, ln1_g, ln1_b, /*blk0=*/9,
        nullptr, y1, nullptr, /*omode=*/0, /*flags=*/2);
    dw_v3<<<dim3(Cch, Bb, 1), 256>>>(y1, y2, BCL, CL, dw_w, dw_b, 9);
    pw_v8<<<dim3(64, Bb, 1), 256, PW_SMEM>>>(
        y2, nullptr, nullptr, nullptr, nullptr, /*imode=*/0,
        pw2_w, pw2_b, ln2_g, ln2_b, ln3_g, ln3_b, /*blk0=*/9,
        query, out, nullptr, /*omode=*/0, /*flags=*/1 | 4);
}